// round 5
// baseline (speedup 1.0000x reference)
#include <cuda_runtime.h>
#include <math.h>

// QuantumTransformerBlock — closed-form quantum ops + f-split FFN, software-pipelined LDS.
// 65536 tokens. 148 blocks x 448 threads. Threads [0,224): f-half 0, [224,448): f-half 1.
// Each thread: 2 adjacent tokens over half the f-range; halves combine via smem exchange.

#define SMEM_BYTES 139392   // 34848 floats: W1i 16400 (1025 rows) + W2i 16384 + b1 2050 + pad

typedef unsigned long long u64;

__device__ __forceinline__ u64 fma2(u64 a, u64 b, u64 c) {
    u64 d; asm("fma.rn.f32x2 %0, %1, %2, %3;" : "=l"(d) : "l"(a), "l"(b), "l"(c)); return d;
}
__device__ __forceinline__ u64 mul2(u64 a, u64 b) {
    u64 d; asm("mul.rn.f32x2 %0, %1, %2;" : "=l"(d) : "l"(a), "l"(b)); return d;
}
__device__ __forceinline__ u64 add2(u64 a, u64 b) {
    u64 d; asm("add.rn.f32x2 %0, %1, %2;" : "=l"(d) : "l"(a), "l"(b)); return d;
}
__device__ __forceinline__ void unpack2(u64 a, float& lo, float& hi) {
    asm("mov.b64 {%0, %1}, %2;" : "=f"(lo), "=f"(hi) : "l"(a));
}
__device__ __forceinline__ u64 pack2(float lo, float hi) {
    u64 d; asm("mov.b64 %0, {%1, %2};" : "=l"(d) : "f"(lo), "f"(hi)); return d;
}

__global__ void __launch_bounds__(448, 1) qtb_kernel(
    const float* __restrict__ x, const float* __restrict__ theta, const float* __restrict__ phi,
    const float* __restrict__ W1, const float* __restrict__ b1,
    const float* __restrict__ W2, const float* __restrict__ b2,
    const float* __restrict__ g1, const float* __restrict__ be1,
    const float* __restrict__ g2, const float* __restrict__ be2,
    float* __restrict__ out)
{
    extern __shared__ float smem[];
    float2* sW1i = (float2*)smem;                   // floats [0,16400): 1025 rows x 8 pairs
    float2* sW2i = (float2*)(smem + 16400);         // floats [16400,32784): 1024 rows x 8 pairs
    float2* sB1p = (float2*)(smem + 32784);         // floats [32784,34834): 1025 pairs

    const int tid = threadIdx.x;

    // ---- preamble: interleaved f-pair weight tables ----
    for (int i = tid; i < 8192; i += 448) {
        int fp = i >> 3, j = i & 7;
        sW1i[i] = make_float2(W1[(fp << 4) + j], W1[(fp << 4) + 8 + j]);
    }
    for (int i = tid; i < 8192; i += 448) {
        int fp = i & 1023, e = i >> 10;
        sW2i[(fp << 3) + e] = *(const float2*)(W2 + (e << 11) + (fp << 1));
    }
    for (int i = tid; i < 1024; i += 448)
        sB1p[i] = ((const float2*)b1)[i];
    if (tid < 8) sW1i[8192 + tid] = make_float2(0.f, 0.f);   // pad row 1024 (prefetch overrun)
    if (tid == 8) sB1p[1024] = make_float2(0.f, 0.f);
    __syncthreads();

    const int  half   = (tid >= 224) ? 1 : 0;       // warp-uniform (boundary at warp 7)
    const int  pl     = tid - (half << 8) + (half << 5);  // tid or tid-224
    const int  gp     = blockIdx.x * 224 + (half ? tid - 224 : tid);
    const bool active = gp < 32768;
    const int  t0     = gp << 1;

    float h0[8], h1[8];
    u64 zz0[8], zz1[8];
    u64 acc0[8] = {0,0,0,0,0,0,0,0};
    u64 acc1[8] = {0,0,0,0,0,0,0,0};
    float pa0[8], pa1[8];

    if (active) {
        float th[8], cph[8], gg[8], bb[8];
        #pragma unroll
        for (int j = 0; j < 8; j++) {
            th[j]  = __ldg(theta + j);
            cph[j] = cosf(__ldg(phi + j));
            gg[j]  = __ldg(g1 + j);
            bb[j]  = __ldg(be1 + j);
        }

        // ---- front: closed-form attn + LN1 + ffn_quantum (both tokens) ----
        #pragma unroll
        for (int tk = 0; tk < 2; tk++) {
            const float* xp = x + (size_t)(t0 + tk) * 8;
            float4 a4 = __ldg((const float4*)xp);
            float4 b4 = __ldg((const float4*)(xp + 4));
            float xv[8] = {a4.x, a4.y, a4.z, a4.w, b4.x, b4.y, b4.z, b4.w};

            float c[8];
            #pragma unroll
            for (int j = 0; j < 8; j++) c[j] = cosf(xv[j] + th[j]);
            float attn[8];
            float pr = c[0];
            #pragma unroll
            for (int j = 1; j < 8; j++) { pr *= c[j]; attn[j] = pr; }
            float qr = c[1];
            #pragma unroll
            for (int j = 2; j < 8; j++) qr *= c[j];
            attn[0] = qr;

            float y[8]; float s = 0.f;
            #pragma unroll
            for (int j = 0; j < 8; j++) { y[j] = xv[j] + attn[j]; s += y[j]; }
            float m = s * 0.125f, v = 0.f;
            #pragma unroll
            for (int j = 0; j < 8; j++) { float d = y[j] - m; v += d * d; }
            float inv = rsqrtf(v * 0.125f + 1e-5f);

            float* hh = tk ? h1 : h0;
            u64*   zz = tk ? zz1 : zz0;
            #pragma unroll
            for (int j = 0; j < 8; j++) {
                hh[j] = (y[j] - m) * inv * gg[j] + bb[j];
                float z = cph[j] * cosf(hh[j]);
                zz[j] = pack2(z, z);
            }
        }

        // ---- FFN over this half's 512 f-pairs, software-pipelined ----
        const int fpbase = half << 9;
        const ulonglong2* w1 = (const ulonglong2*)sW1i + ((size_t)fpbase << 2);
        const ulonglong2* w2 = (const ulonglong2*)sW2i + ((size_t)fpbase << 2);
        const u64*        bp = (const u64*)sB1p + fpbase;

        // prologue: load iteration 0's A + bias
        ulonglong2 A0 = w1[0], A1 = w1[1], A2 = w1[2], A3 = w1[3];
        u64 bpv = bp[0];

        #pragma unroll 2
        for (int fp = 0; fp < 512; fp++) {
            // issue all loads first: C for THIS iter, A/bias for NEXT iter
            ulonglong2 C0 = w2[0], C1 = w2[1], C2 = w2[2], C3 = w2[3]; w2 += 4;
            w1 += 4;
            ulonglong2 nA0 = w1[0], nA1 = w1[1], nA2 = w1[2], nA3 = w1[3]; // row 1024 = pad
            u64 nbp = bp[fp + 1];

            // gemm1 (consumes pre-loaded A) — hides the loads above
            u64 pA = fma2(zz0[0], A0.x, bpv);
            u64 pB = mul2(zz0[4], A2.x);
            u64 qA = fma2(zz1[0], A0.x, bpv);
            u64 qB = mul2(zz1[4], A2.x);
            pA = fma2(zz0[1], A0.y, pA);
            pB = fma2(zz0[5], A2.y, pB);
            qA = fma2(zz1[1], A0.y, qA);
            qB = fma2(zz1[5], A2.y, qB);
            pA = fma2(zz0[2], A1.x, pA);
            pB = fma2(zz0[6], A3.x, pB);
            qA = fma2(zz1[2], A1.x, qA);
            qB = fma2(zz1[6], A3.x, qB);
            pA = fma2(zz0[3], A1.y, pA);
            pB = fma2(zz0[7], A3.y, pB);
            qA = fma2(zz1[3], A1.y, qA);
            qB = fma2(zz1[7], A3.y, qB);

            float l0, u0, l1, u1;
            unpack2(add2(pA, pB), l0, u0);
            unpack2(add2(qA, qB), l1, u1);
            u64 r0 = pack2(fmaxf(l0, 0.f), fmaxf(u0, 0.f));
            u64 r1 = pack2(fmaxf(l1, 0.f), fmaxf(u1, 0.f));

            // gemm2 (C latency covered by gemm1)
            acc0[0] = fma2(r0, C0.x, acc0[0]);
            acc1[0] = fma2(r1, C0.x, acc1[0]);
            acc0[1] = fma2(r0, C0.y, acc0[1]);
            acc1[1] = fma2(r1, C0.y, acc1[1]);
            acc0[2] = fma2(r0, C1.x, acc0[2]);
            acc1[2] = fma2(r1, C1.x, acc1[2]);
            acc0[3] = fma2(r0, C1.y, acc0[3]);
            acc1[3] = fma2(r1, C1.y, acc1[3]);
            acc0[4] = fma2(r0, C2.x, acc0[4]);
            acc1[4] = fma2(r1, C2.x, acc1[4]);
            acc0[5] = fma2(r0, C2.y, acc0[5]);
            acc1[5] = fma2(r1, C2.y, acc1[5]);
            acc0[6] = fma2(r0, C3.x, acc0[6]);
            acc1[6] = fma2(r1, C3.x, acc1[6]);
            acc0[7] = fma2(r0, C3.y, acc0[7]);
            acc1[7] = fma2(r1, C3.y, acc1[7]);

            A0 = nA0; A1 = nA1; A2 = nA2; A3 = nA3; bpv = nbp;
        }

        #pragma unroll
        for (int e = 0; e < 8; e++) {
            float lo, hi;
            unpack2(acc0[e], lo, hi); pa0[e] = lo + hi;
            unpack2(acc1[e], lo, hi); pa1[e] = lo + hi;
        }
    }

    // ---- exchange: half 1 writes partials, half 0 combines + epilogue ----
    __syncthreads();                                // weights no longer needed
    float* xch = smem;                              // reuse weight region; slot stride 9
    if (active && half == 1) {
        int pidx = (tid - 224) * 2;
        float* s0 = xch + (size_t)(pidx + 0) * 9;   // max (447)*9+7 = 4030 < 34848
        float* s1 = xch + (size_t)(pidx + 1) * 9;
        #pragma unroll
        for (int e = 0; e < 8; e++) { s0[e] = pa0[e]; s1[e] = pa1[e]; }
    }
    __syncthreads();

    if (active && half == 0) {
        float g2v[8], b2e[8], bb2[8];
        #pragma unroll
        for (int j = 0; j < 8; j++) {
            g2v[j] = __ldg(g2 + j);
            b2e[j] = __ldg(be2 + j);
            bb2[j] = __ldg(b2 + j);
        }
        #pragma unroll
        for (int tk = 0; tk < 2; tk++) {
            float* pa = tk ? pa1 : pa0;
            float* hh = tk ? h1 : h0;
            const float* so = xch + (size_t)(tid * 2 + tk) * 9;
            float w[8]; float s2 = 0.f;
            #pragma unroll
            for (int e = 0; e < 8; e++) {
                w[e] = hh[e] + pa[e] + so[e] + bb2[e];
                s2 += w[e];
            }
            float m2 = s2 * 0.125f, v2 = 0.f;
            #pragma unroll
            for (int e = 0; e < 8; e++) { float d = w[e] - m2; v2 += d * d; }
            float inv2 = rsqrtf(v2 * 0.125f + 1e-5f);
            float o[8];
            #pragma unroll
            for (int e = 0; e < 8; e++) o[e] = (w[e] - m2) * inv2 * g2v[e] + b2e[e];
            float* op = out + (size_t)(t0 + tk) * 8;
            *(float4*)op       = make_float4(o[0], o[1], o[2], o[3]);
            *(float4*)(op + 4) = make_float4(o[4], o[5], o[6], o[7]);
        }
    }
}

extern "C" void kernel_launch(void* const* d_in, const int* in_sizes, int n_in,
                              void* d_out, int out_size) {
    const float* x      = (const float*)d_in[0];
    const float* theta  = (const float*)d_in[1];
    const float* phi    = (const float*)d_in[2];
    const float* W1     = (const float*)d_in[3];
    const float* b1     = (const float*)d_in[4];
    const float* W2     = (const float*)d_in[5];
    const float* b2     = (const float*)d_in[6];
    const float* gamma1 = (const float*)d_in[7];
    const float* beta1  = (const float*)d_in[8];
    const float* gamma2 = (const float*)d_in[9];
    const float* beta2  = (const float*)d_in[10];
    float* out = (float*)d_out;

    cudaFuncSetAttribute(qtb_kernel, cudaFuncAttributeMaxDynamicSharedMemorySize, SMEM_BYTES);
    qtb_kernel<<<148, 448, SMEM_BYTES>>>(x, theta, phi, W1, b1, W2, b2,
                                         gamma1, beta1, gamma2, beta2, out);
}

// round 6
// speedup vs baseline: 1.6899x; 1.6899x over previous
#include <cuda_runtime.h>
#include <math.h>
#include <stdint.h>

// QuantumTransformerBlock — closed-form quantum ops + tensor-core FFN (mma.sync tf32).
// GEMM1 (K=8) in 3-term split-tf32 for precision; GEMM2 (K=2048) single tf32.
// 148 blocks x 448 threads (14 warps). Warp gid handles tile16 gid and gid+2072.

#define TPB   448
#define NWARP 14
#define GRID  148
#define TOTAL_GIDS (GRID * NWARP)          // 2072
#define NTILES 4096
#define TWO_CUT (NTILES - TOTAL_GIDS)      // 2024: gid < this -> handles 2 tiles

// smem float offsets
#define B1H_OFF  0        // 16384 floats: [256 c][32 lane] float2 (W1 hi pairs)
#define B1L_OFF  16384    // 16384 floats: W1 lo
#define B2_OFF   32768    // 16384 floats: [256 c][32 lane] float2 (W2 tf32, pi-permuted rows)
#define BIAS_OFF 49152    // 2048 floats:  [256 c][4 t] float2 (b1 col pairs, full fp32)
#define SZ_OFF   51200    // 3584 floats:  [14 warp][2 tile][16 tok][8 j] (reused as epi scratch)
#define SMEM_FLOATS (SZ_OFF + NWARP * 256)
#define SMEM_BYTES (SMEM_FLOATS * 4)       // 219136

__device__ __forceinline__ uint32_t tf32_of(float v) {
    uint32_t u; asm("cvt.rna.tf32.f32 %0, %1;" : "=r"(u) : "f"(v)); return u;
}

#define MMA_TF32(D0,D1,D2,D3, A0,A1,A2,A3, B0,B1, C0,C1,C2,C3) \
  asm("mma.sync.aligned.m16n8k8.row.col.f32.tf32.tf32.f32 " \
      "{%0,%1,%2,%3}, {%4,%5,%6,%7}, {%8,%9}, {%10,%11,%12,%13};" \
      : "=f"(D0),"=f"(D1),"=f"(D2),"=f"(D3) \
      : "r"(A0),"r"(A1),"r"(A2),"r"(A3), "r"(B0),"r"(B1), \
        "f"(C0),"f"(C1),"f"(C2),"f"(C3))

__global__ void __launch_bounds__(TPB, 1) qtb_kernel(
    const float* __restrict__ x, const float* __restrict__ theta, const float* __restrict__ phi,
    const float* __restrict__ W1, const float* __restrict__ b1,
    const float* __restrict__ W2, const float* __restrict__ b2,
    const float* __restrict__ g1, const float* __restrict__ be1,
    const float* __restrict__ g2, const float* __restrict__ be2,
    float* __restrict__ out)
{
    extern __shared__ float smem[];
    const int tid = threadIdx.x;

    // ================= preamble: weight tables in mma-fragment layout =================
    // GEMM1 B-frag (b0=B[t][g], b1=B[t+4][g]; B=W1T so B[j][f]): lane(g,t) of chunk c
    // holds (W1[c*8+g][t], W1[c*8+g][t+4]), split into tf32 hi/lo.
    for (int i = tid; i < 8192; i += TPB) {
        int c = i >> 5, r = i & 31, gq = r >> 2, tq = r & 3;
        int f = c * 8 + gq;
        float va = W1[f * 8 + tq];
        float vb = W1[f * 8 + tq + 4];
        uint32_t ah = tf32_of(va), bh = tf32_of(vb);
        uint32_t al = tf32_of(va - __uint_as_float(ah));
        uint32_t bl = tf32_of(vb - __uint_as_float(bh));
        ((float2*)(smem + B1H_OFF))[i] = make_float2(__uint_as_float(ah), __uint_as_float(bh));
        ((float2*)(smem + B1L_OFF))[i] = make_float2(__uint_as_float(al), __uint_as_float(bl));
    }
    // GEMM2 B-frag with k-permutation pi(t)=2t, pi(t+4)=2t+1:
    // lane(g,t) of chunk c holds (W2[g][c*8+2t], W2[g][c*8+2t+1]) as tf32.
    for (int i = tid; i < 8192; i += TPB) {
        int c = i >> 5, r = i & 31, gq = r >> 2, tq = r & 3;
        int f0 = c * 8 + 2 * tq;
        uint32_t v0 = tf32_of(W2[gq * 2048 + f0]);
        uint32_t v1 = tf32_of(W2[gq * 2048 + f0 + 1]);
        ((float2*)(smem + B2_OFF))[i] = make_float2(__uint_as_float(v0), __uint_as_float(v1));
    }
    // bias pairs per (c, t): D-frag cols (2t, 2t+1). Full fp32 (goes in mma C operand).
    for (int i = tid; i < 1024; i += TPB) {
        int c = i >> 2, tq = i & 3;
        ((float2*)(smem + BIAS_OFF))[i] = make_float2(b1[c * 8 + 2 * tq], b1[c * 8 + 2 * tq + 1]);
    }
    __syncthreads();

    const int wid  = tid >> 5, lane = tid & 31;
    const int g    = lane >> 2, t = lane & 3;
    const int gid  = blockIdx.x * NWARP + wid;
    const bool two = gid < TWO_CUT;
    const int tau0 = gid;
    const int tau1 = two ? gid + TOTAL_GIDS : gid;   // dup tile0 if single (writes gated)

    // ================= front: closed-form attn + LN1 + ffn_quantum =================
    // lanes 0-15 -> tile0 tokens, lanes 16-31 -> tile1 tokens. One token per lane.
    const int lh = lane >> 4, ll = lane & 15;
    const int tok = (lh ? tau1 : tau0) * 16 + ll;

    float h[8];
    {
        float th_[8], cph[8], gg_[8], bb_[8];
        #pragma unroll
        for (int j = 0; j < 8; j++) {
            th_[j] = __ldg(theta + j);
            cph[j] = cosf(__ldg(phi + j));
            gg_[j] = __ldg(g1 + j);
            bb_[j] = __ldg(be1 + j);
        }
        const float* xp = x + (size_t)tok * 8;
        float4 a4 = __ldg((const float4*)xp);
        float4 b4 = __ldg((const float4*)(xp + 4));
        float xv[8] = {a4.x, a4.y, a4.z, a4.w, b4.x, b4.y, b4.z, b4.w};

        float c_[8];
        #pragma unroll
        for (int j = 0; j < 8; j++) c_[j] = cosf(xv[j] + th_[j]);
        float attn[8];
        float pr = c_[0];
        #pragma unroll
        for (int j = 1; j < 8; j++) { pr *= c_[j]; attn[j] = pr; }
        float qr = c_[1];
        #pragma unroll
        for (int j = 2; j < 8; j++) qr *= c_[j];
        attn[0] = qr;

        float y[8]; float s = 0.f;
        #pragma unroll
        for (int j = 0; j < 8; j++) { y[j] = xv[j] + attn[j]; s += y[j]; }
        float m = s * 0.125f, v = 0.f;
        #pragma unroll
        for (int j = 0; j < 8; j++) { float d = y[j] - m; v += d * d; }
        float inv = rsqrtf(v * 0.125f + 1e-5f);

        float* sz = smem + SZ_OFF + wid * 256 + lh * 128 + ll * 8;
        #pragma unroll
        for (int j = 0; j < 8; j++) {
            h[j] = (y[j] - m) * inv * gg_[j] + bb_[j];
            sz[j] = cph[j] * cosf(h[j]);            // z
        }
    }
    __syncwarp();

    // ================= A-frags for GEMM1 (Z, 16x8), split hi/lo =================
    const float* z0 = smem + SZ_OFF + wid * 256;
    const float* z1 = z0 + 128;
    uint32_t ah0[4], al0[4], ah1[4], al1[4];
    {
        int idx[4] = { g*8 + t, (g+8)*8 + t, g*8 + t + 4, (g+8)*8 + t + 4 };
        #pragma unroll
        for (int k = 0; k < 4; k++) {
            float a = z0[idx[k]];
            ah0[k] = tf32_of(a); al0[k] = tf32_of(a - __uint_as_float(ah0[k]));
            float b = z1[idx[k]];
            ah1[k] = tf32_of(b); al1[k] = tf32_of(b - __uint_as_float(ah1[k]));
        }
    }
    __syncwarp();   // sZ now reusable as epilogue scratch

    // ================= chunk loop: 256 chunks of 8 f =================
    float acc0_0 = 0.f, acc0_1 = 0.f, acc0_2 = 0.f, acc0_3 = 0.f;
    float acc1_0 = 0.f, acc1_1 = 0.f, acc1_2 = 0.f, acc1_3 = 0.f;
    const float2* pB1h = (const float2*)(smem + B1H_OFF);
    const float2* pB1l = (const float2*)(smem + B1L_OFF);
    const float2* pB2  = (const float2*)(smem + B2_OFF);
    const float2* pBia = (const float2*)(smem + BIAS_OFF);

    #pragma unroll 2
    for (int c = 0; c < 256; c++) {
        float2 b1hf = pB1h[(c << 5) + lane];
        float2 b1lf = pB1l[(c << 5) + lane];
        float2 b2f  = pB2 [(c << 5) + lane];
        float2 bia  = pBia[(c << 2) + t];
        uint32_t B1H0 = __float_as_uint(b1hf.x), B1H1 = __float_as_uint(b1hf.y);
        uint32_t B1L0 = __float_as_uint(b1lf.x), B1L1 = __float_as_uint(b1lf.y);
        uint32_t B20  = __float_as_uint(b2f.x),  B21  = __float_as_uint(b2f.y);

        // ---- tile 0 ----
        float d0, d1, d2, d3;
        MMA_TF32(d0,d1,d2,d3, ah0[0],ah0[1],ah0[2],ah0[3], B1H0,B1H1, bia.x,bia.y,bia.x,bia.y);
        MMA_TF32(d0,d1,d2,d3, al0[0],al0[1],al0[2],al0[3], B1H0,B1H1, d0,d1,d2,d3);
        MMA_TF32(d0,d1,d2,d3, ah0[0],ah0[1],ah0[2],ah0[3], B1L0,B1L1, d0,d1,d2,d3);
        d0 = fmaxf(d0, 0.f); d1 = fmaxf(d1, 0.f); d2 = fmaxf(d2, 0.f); d3 = fmaxf(d3, 0.f);
        uint32_t p0 = tf32_of(d0), p1 = tf32_of(d1), p2 = tf32_of(d2), p3 = tf32_of(d3);
        // A2-frag = (d0,d2,d1,d3) thanks to pi-permuted B2 rows
        MMA_TF32(acc0_0,acc0_1,acc0_2,acc0_3, p0,p2,p1,p3, B20,B21, acc0_0,acc0_1,acc0_2,acc0_3);

        // ---- tile 1 ----
        MMA_TF32(d0,d1,d2,d3, ah1[0],ah1[1],ah1[2],ah1[3], B1H0,B1H1, bia.x,bia.y,bia.x,bia.y);
        MMA_TF32(d0,d1,d2,d3, al1[0],al1[1],al1[2],al1[3], B1H0,B1H1, d0,d1,d2,d3);
        MMA_TF32(d0,d1,d2,d3, ah1[0],ah1[1],ah1[2],ah1[3], B1L0,B1L1, d0,d1,d2,d3);
        d0 = fmaxf(d0, 0.f); d1 = fmaxf(d1, 0.f); d2 = fmaxf(d2, 0.f); d3 = fmaxf(d3, 0.f);
        p0 = tf32_of(d0); p1 = tf32_of(d1); p2 = tf32_of(d2); p3 = tf32_of(d3);
        MMA_TF32(acc1_0,acc1_1,acc1_2,acc1_3, p0,p2,p1,p3, B20,B21, acc1_0,acc1_1,acc1_2,acc1_3);
    }

    // ================= epilogue: per-token residual + b2 + LN2 =================
    // acc frag: c0=F[g][2t], c1=F[g][2t+1], c2=F[g+8][2t], c3=F[g+8][2t+1]
    float* sE0 = smem + SZ_OFF + wid * 256;        // reuse z region as scratch
    float* sE1 = sE0 + 128;
    sE0[g*8 + 2*t]       = acc0_0;
    sE0[g*8 + 2*t + 1]   = acc0_1;
    sE0[(g+8)*8 + 2*t]   = acc0_2;
    sE0[(g+8)*8 + 2*t+1] = acc0_3;
    sE1[g*8 + 2*t]       = acc1_0;
    sE1[g*8 + 2*t + 1]   = acc1_1;
    sE1[(g+8)*8 + 2*t]   = acc1_2;
    sE1[(g+8)*8 + 2*t+1] = acc1_3;
    __syncwarp();

    if (lh == 0 || two) {                          // gate duplicate tile1 writes
        const float* sE = lh ? sE1 : sE0;
        float w[8]; float s2 = 0.f;
        #pragma unroll
        for (int e = 0; e < 8; e++) {
            w[e] = h[e] + sE[ll*8 + e] + __ldg(b2 + e);
            s2 += w[e];
        }
        float m2 = s2 * 0.125f, v2 = 0.f;
        #pragma unroll
        for (int e = 0; e < 8; e++) { float d = w[e] - m2; v2 += d * d; }
        float inv2 = rsqrtf(v2 * 0.125f + 1e-5f);
        float o[8];
        #pragma unroll
        for (int e = 0; e < 8; e++)
            o[e] = (w[e] - m2) * inv2 * __ldg(g2 + e) + __ldg(be2 + e);
        float* op = out + (size_t)tok * 8;
        *(float4*)op       = make_float4(o[0], o[1], o[2], o[3]);
        *(float4*)(op + 4) = make_float4(o[4], o[5], o[6], o[7]);
    }
}

extern "C" void kernel_launch(void* const* d_in, const int* in_sizes, int n_in,
                              void* d_out, int out_size) {
    const float* x      = (const float*)d_in[0];
    const float* theta  = (const float*)d_in[1];
    const float* phi    = (const float*)d_in[2];
    const float* W1     = (const float*)d_in[3];
    const float* b1     = (const float*)d_in[4];
    const float* W2     = (const float*)d_in[5];
    const float* b2     = (const float*)d_in[6];
    const float* gamma1 = (const float*)d_in[7];
    const float* beta1  = (const float*)d_in[8];
    const float* gamma2 = (const float*)d_in[9];
    const float* beta2  = (const float*)d_in[10];
    float* out = (float*)d_out;

    cudaFuncSetAttribute(qtb_kernel, cudaFuncAttributeMaxDynamicSharedMemorySize, SMEM_BYTES);
    qtb_kernel<<<GRID, TPB, SMEM_BYTES>>>(x, theta, phi, W1, b1, W2, b2,
                                          gamma1, beta1, gamma2, beta2, out);
}

// round 7
// speedup vs baseline: 2.3405x; 1.3850x over previous
#include <cuda_runtime.h>
#include <cuda_fp16.h>
#include <math.h>
#include <stdint.h>

// QuantumTransformerBlock — closed-form quantum ops + fp16 split-precision tensor-core FFN.
// GEMM1: 2x mma.m16n8k16.f16 (hi/lo split of z and W1, ~fp32-exact).
// GEMM2: 1x mma.m16n8k8.f16 (pi-permuted W2 rows -> D-frag feeds A-frag with zero shuffles).
// 148 blocks x 512 threads (16 warps). gid < 1728 warps handle a second tile (exact 4096 cover).

#define TPB   512
#define NWARP 16
#define GRID  148
#define TOTAL_GIDS (GRID * NWARP)          // 2368
#define NTILES 4096
#define TWO_CUT (NTILES - TOTAL_GIDS)      // 1728

// smem float offsets
#define W1H_OFF  0        // 8192 u32: [256 c][32 lane] f16x2 (W1 hi pair)
#define W1L_OFF  8192     // 8192 u32: W1 lo pair
#define W2_OFF   16384    // 8192 u32: [256 c][32 lane] f16x2 (W2, pi-permuted rows)
#define BIAS_OFF 24576    // 2048 floats: [256 c][4 t] float2 (b1 col pairs, fp32)
#define SZ_OFF   26624    // 4096 floats: [16 warp][2 tile][16 tok][8 j] (reused as epi scratch)
#define SMEM_FLOATS (SZ_OFF + NWARP * 256)
#define SMEM_BYTES (SMEM_FLOATS * 4)       // 122880

__device__ __forceinline__ uint32_t pack_f16x2(float lo, float hi) {
    uint32_t d; asm("cvt.rn.f16x2.f32 %0, %1, %2;" : "=r"(d) : "f"(hi), "f"(lo)); return d;
}
__device__ __forceinline__ float rnd16(float v) {
    return __half2float(__float2half_rn(v));
}

#define MMA16_F16(D0,D1,D2,D3, A0,A1,A2,A3, B0,B1, C0,C1,C2,C3) \
  asm("mma.sync.aligned.m16n8k16.row.col.f32.f16.f16.f32 " \
      "{%0,%1,%2,%3}, {%4,%5,%6,%7}, {%8,%9}, {%10,%11,%12,%13};" \
      : "=f"(D0),"=f"(D1),"=f"(D2),"=f"(D3) \
      : "r"(A0),"r"(A1),"r"(A2),"r"(A3), "r"(B0),"r"(B1), \
        "f"(C0),"f"(C1),"f"(C2),"f"(C3))

#define MMA8_F16(D0,D1,D2,D3, A0,A1, B0, C0,C1,C2,C3) \
  asm("mma.sync.aligned.m16n8k8.row.col.f32.f16.f16.f32 " \
      "{%0,%1,%2,%3}, {%4,%5}, {%6}, {%7,%8,%9,%10};" \
      : "=f"(D0),"=f"(D1),"=f"(D2),"=f"(D3) \
      : "r"(A0),"r"(A1), "r"(B0), \
        "f"(C0),"f"(C1),"f"(C2),"f"(C3))

__global__ void __launch_bounds__(TPB, 1) qtb_kernel(
    const float* __restrict__ x, const float* __restrict__ theta, const float* __restrict__ phi,
    const float* __restrict__ W1, const float* __restrict__ b1,
    const float* __restrict__ W2, const float* __restrict__ b2,
    const float* __restrict__ g1, const float* __restrict__ be1,
    const float* __restrict__ g2, const float* __restrict__ be2,
    float* __restrict__ out)
{
    extern __shared__ float smem[];
    const int tid = threadIdx.x;
    uint32_t* pW1h = (uint32_t*)(smem + W1H_OFF);
    uint32_t* pW1l = (uint32_t*)(smem + W1L_OFF);
    uint32_t* pW2  = (uint32_t*)(smem + W2_OFF);

    // ================= preamble: weight tables in mma-fragment layout =================
    // GEMM1 B-frag: lane(g,t) of chunk c holds W1[f=c*8+g][j=2t], [j=2t+1] hi/lo fp16 pairs.
    for (int i = tid; i < 8192; i += TPB) {
        int c = i >> 5, r = i & 31, gq = r >> 2, tq = r & 3;
        int f = c * 8 + gq;
        float w0 = W1[f * 8 + 2 * tq];
        float w1 = W1[f * 8 + 2 * tq + 1];
        float h0 = rnd16(w0), h1 = rnd16(w1);
        pW1h[i] = pack_f16x2(h0, h1);
        pW1l[i] = pack_f16x2(w0 - h0, w1 - h1);
    }
    // GEMM2 B-frag, pi-permuted rows: lane(g,t) holds (W2[e=g][c*8+2t], W2[g][c*8+2t+1]) fp16.
    for (int i = tid; i < 8192; i += TPB) {
        int c = i >> 5, r = i & 31, gq = r >> 2, tq = r & 3;
        int f0 = c * 8 + 2 * tq;
        pW2[i] = pack_f16x2(W2[gq * 2048 + f0], W2[gq * 2048 + f0 + 1]);
    }
    // bias pairs per (c, t): D-frag cols (2t, 2t+1), full fp32 (mma C operand).
    for (int i = tid; i < 1024; i += TPB) {
        int c = i >> 2, tq = i & 3;
        ((float2*)(smem + BIAS_OFF))[i] = make_float2(b1[c * 8 + 2 * tq], b1[c * 8 + 2 * tq + 1]);
    }
    __syncthreads();

    const int wid  = tid >> 5, lane = tid & 31;
    const int g    = lane >> 2, t = lane & 3;
    const int gid  = blockIdx.x * NWARP + wid;
    const bool two = gid < TWO_CUT;
    const int tau0 = gid;
    const int tau1 = two ? gid + TOTAL_GIDS : gid;   // dup tile0 if single (writes gated)

    // ================= front: closed-form attn + LN1 + ffn_quantum =================
    const int lh = lane >> 4, ll = lane & 15;
    const int tok = (lh ? tau1 : tau0) * 16 + ll;

    float h[8];
    {
        float th_[8], cph[8], gg_[8], bb_[8];
        #pragma unroll
        for (int j = 0; j < 8; j++) {
            th_[j] = __ldg(theta + j);
            cph[j] = cosf(__ldg(phi + j));
            gg_[j] = __ldg(g1 + j);
            bb_[j] = __ldg(be1 + j);
        }
        const float* xp = x + (size_t)tok * 8;
        float4 a4 = __ldg((const float4*)xp);
        float4 b4 = __ldg((const float4*)(xp + 4));
        float xv[8] = {a4.x, a4.y, a4.z, a4.w, b4.x, b4.y, b4.z, b4.w};

        float c_[8];
        #pragma unroll
        for (int j = 0; j < 8; j++) c_[j] = cosf(xv[j] + th_[j]);
        float attn[8];
        float pr = c_[0];
        #pragma unroll
        for (int j = 1; j < 8; j++) { pr *= c_[j]; attn[j] = pr; }
        float qr = c_[1];
        #pragma unroll
        for (int j = 2; j < 8; j++) qr *= c_[j];
        attn[0] = qr;

        float y[8]; float s = 0.f;
        #pragma unroll
        for (int j = 0; j < 8; j++) { y[j] = xv[j] + attn[j]; s += y[j]; }
        float m = s * 0.125f, v = 0.f;
        #pragma unroll
        for (int j = 0; j < 8; j++) { float d = y[j] - m; v += d * d; }
        float inv = rsqrtf(v * 0.125f + 1e-5f);

        float* sz = smem + SZ_OFF + wid * 256 + lh * 128 + ll * 8;
        #pragma unroll
        for (int j = 0; j < 8; j++) {
            h[j] = (y[j] - m) * inv * gg_[j] + bb_[j];
            sz[j] = cph[j] * cosf(h[j]);            // z
        }
    }
    __syncwarp();

    // ================= A-frags for GEMM1 (Z 16x16-virtual: k 0-7 = zh, k 8-15 = zl) ========
    const float* z0 = smem + SZ_OFF + wid * 256;
    const float* z1 = z0 + 128;
    uint32_t A0h_g, A0h_G, A0l_g, A0l_G;            // tile0: rows g / g+8, hi / lo
    uint32_t A1h_g, A1h_G, A1l_g, A1l_G;            // tile1
    {
        int i0 = g * 8 + 2 * t, i1 = i0 + 1;
        int I0 = (g + 8) * 8 + 2 * t, I1 = I0 + 1;
        float a, b, ha, hb;
        a = z0[i0]; b = z0[i1]; ha = rnd16(a); hb = rnd16(b);
        A0h_g = pack_f16x2(ha, hb); A0l_g = pack_f16x2(a - ha, b - hb);
        a = z0[I0]; b = z0[I1]; ha = rnd16(a); hb = rnd16(b);
        A0h_G = pack_f16x2(ha, hb); A0l_G = pack_f16x2(a - ha, b - hb);
        a = z1[i0]; b = z1[i1]; ha = rnd16(a); hb = rnd16(b);
        A1h_g = pack_f16x2(ha, hb); A1l_g = pack_f16x2(a - ha, b - hb);
        a = z1[I0]; b = z1[I1]; ha = rnd16(a); hb = rnd16(b);
        A1h_G = pack_f16x2(ha, hb); A1l_G = pack_f16x2(a - ha, b - hb);
    }
    __syncwarp();   // sZ now reusable as epilogue scratch

    // ================= chunk loop: 256 chunks of 8 f =================
    float acc0_0 = 0.f, acc0_1 = 0.f, acc0_2 = 0.f, acc0_3 = 0.f;
    float acc1_0 = 0.f, acc1_1 = 0.f, acc1_2 = 0.f, acc1_3 = 0.f;
    const float2* pBia = (const float2*)(smem + BIAS_OFF);

    #pragma unroll 4
    for (int c = 0; c < 256; c++) {
        uint32_t bWh = pW1h[(c << 5) + lane];
        uint32_t bWl = pW1l[(c << 5) + lane];
        uint32_t bW2 = pW2 [(c << 5) + lane];
        float2   bia = pBia[(c << 2) + t];

        // ---- tile 0 ----
        float d0, d1, d2, d3;
        MMA16_F16(d0,d1,d2,d3, A0h_g,A0h_G,A0l_g,A0l_G, bWh,bWh, bia.x,bia.y,bia.x,bia.y);
        MMA16_F16(d0,d1,d2,d3, A0h_g,A0h_G,A0l_g,A0l_G, bWl,bWl, d0,d1,d2,d3);
        d0 = fmaxf(d0, 0.f); d1 = fmaxf(d1, 0.f); d2 = fmaxf(d2, 0.f); d3 = fmaxf(d3, 0.f);
        uint32_t p0 = pack_f16x2(d0, d1);           // = A-frag {F[g][2t], F[g][2t+1]}
        uint32_t p1 = pack_f16x2(d2, d3);
        MMA8_F16(acc0_0,acc0_1,acc0_2,acc0_3, p0,p1, bW2, acc0_0,acc0_1,acc0_2,acc0_3);

        // ---- tile 1 ----
        MMA16_F16(d0,d1,d2,d3, A1h_g,A1h_G,A1l_g,A1l_G, bWh,bWh, bia.x,bia.y,bia.x,bia.y);
        MMA16_F16(d0,d1,d2,d3, A1h_g,A1h_G,A1l_g,A1l_G, bWl,bWl, d0,d1,d2,d3);
        d0 = fmaxf(d0, 0.f); d1 = fmaxf(d1, 0.f); d2 = fmaxf(d2, 0.f); d3 = fmaxf(d3, 0.f);
        p0 = pack_f16x2(d0, d1);
        p1 = pack_f16x2(d2, d3);
        MMA8_F16(acc1_0,acc1_1,acc1_2,acc1_3, p0,p1, bW2, acc1_0,acc1_1,acc1_2,acc1_3);
    }

    // ================= epilogue: per-token residual + b2 + LN2 =================
    float* sE0 = smem + SZ_OFF + wid * 256;        // reuse z region as scratch
    float* sE1 = sE0 + 128;
    sE0[g*8 + 2*t]       = acc0_0;
    sE0[g*8 + 2*t + 1]   = acc0_1;
    sE0[(g+8)*8 + 2*t]   = acc0_2;
    sE0[(g+8)*8 + 2*t+1] = acc0_3;
    sE1[g*8 + 2*t]       = acc1_0;
    sE1[g*8 + 2*t + 1]   = acc1_1;
    sE1[(g+8)*8 + 2*t]   = acc1_2;
    sE1[(g+8)*8 + 2*t+1] = acc1_3;
    __syncwarp();

    if (lh == 0 || two) {                          // gate duplicate tile1 writes
        const float* sE = lh ? sE1 : sE0;
        float w[8]; float s2 = 0.f;
        #pragma unroll
        for (int e = 0; e < 8; e++) {
            w[e] = h[e] + sE[ll*8 + e] + __ldg(b2 + e);
            s2 += w[e];
        }
        float m2 = s2 * 0.125f, v2 = 0.f;
        #pragma unroll
        for (int e = 0; e < 8; e++) { float d = w[e] - m2; v2 += d * d; }
        float inv2 = rsqrtf(v2 * 0.125f + 1e-5f);
        float o[8];
        #pragma unroll
        for (int e = 0; e < 8; e++)
            o[e] = (w[e] - m2) * inv2 * __ldg(g2 + e) + __ldg(be2 + e);
        float* op = out + (size_t)tok * 8;
        *(float4*)op       = make_float4(o[0], o[1], o[2], o[3]);
        *(float4*)(op + 4) = make_float4(o[4], o[5], o[6], o[7]);
    }
}

extern "C" void kernel_launch(void* const* d_in, const int* in_sizes, int n_in,
                              void* d_out, int out_size) {
    const float* x      = (const float*)d_in[0];
    const float* theta  = (const float*)d_in[1];
    const float* phi    = (const float*)d_in[2];
    const float* W1     = (const float*)d_in[3];
    const float* b1     = (const float*)d_in[4];
    const float* W2     = (const float*)d_in[5];
    const float* b2     = (const float*)d_in[6];
    const float* gamma1 = (const float*)d_in[7];
    const float* beta1  = (const float*)d_in[8];
    const float* gamma2 = (const float*)d_in[9];
    const float* beta2  = (const float*)d_in[10];
    float* out = (float*)d_out;

    cudaFuncSetAttribute(qtb_kernel, cudaFuncAttributeMaxDynamicSharedMemorySize, SMEM_BYTES);
    qtb_kernel<<<GRID, TPB, SMEM_BYTES>>>(x, theta, phi, W1, b1, W2, b2,
                                          gamma1, beta1, gamma2, beta2, out);
}

// round 8
// speedup vs baseline: 2.4480x; 1.0459x over previous
#include <cuda_runtime.h>
#include <cuda_fp16.h>
#include <math.h>
#include <stdint.h>

// QuantumTransformerBlock — closed-form quantum ops + fp16 split-precision tensor-core FFN.
// GEMM1: 2x independent mma.m16n8k16.f16 (hi/lo) merged by FADD; GEMM2: mma.m16n8k8.f16
// with dual accumulators. Balanced tile map: block b owns tiles b*28..b*28+27
// (warps 0-15 -> first 16, warps 0-11 -> next 12); single-tile warps run a half loop.

#define TPB   512
#define NWARP 16
#define GRID  148
#define NTILES 4096
#define TPB_TILES 28

// smem float offsets
#define W1H_OFF  0        // 8192 u32: [256 c][32 lane] f16x2 (W1 hi pair)
#define W1L_OFF  8192     // 8192 u32: W1 lo pair
#define W2_OFF   16384    // 8192 u32: [256 c][32 lane] f16x2 (W2, pi-permuted rows)
#define BIAS_OFF 24576    // 2048 floats: [256 c][4 t] float2 (b1 col pairs, fp32)
#define SZ_OFF   26624    // 4096 floats: [16 warp][2 tile][16 tok][8 j] (reused as epi scratch)
#define SMEM_FLOATS (SZ_OFF + NWARP * 256)
#define SMEM_BYTES (SMEM_FLOATS * 4)       // 122880

__device__ __forceinline__ uint32_t pack_f16x2(float lo, float hi) {
    uint32_t d; asm("cvt.rn.f16x2.f32 %0, %1, %2;" : "=r"(d) : "f"(hi), "f"(lo)); return d;
}
__device__ __forceinline__ uint32_t hmax2z(uint32_t a) {
    uint32_t d; asm("max.f16x2 %0, %1, %2;" : "=r"(d) : "r"(a), "r"(0u)); return d;
}
__device__ __forceinline__ float rnd16(float v) {
    return __half2float(__float2half_rn(v));
}

#define MMA16_F16(D0,D1,D2,D3, A0,A1,A2,A3, B0,B1, C0,C1,C2,C3) \
  asm("mma.sync.aligned.m16n8k16.row.col.f32.f16.f16.f32 " \
      "{%0,%1,%2,%3}, {%4,%5,%6,%7}, {%8,%9}, {%10,%11,%12,%13};" \
      : "=f"(D0),"=f"(D1),"=f"(D2),"=f"(D3) \
      : "r"(A0),"r"(A1),"r"(A2),"r"(A3), "r"(B0),"r"(B1), \
        "f"(C0),"f"(C1),"f"(C2),"f"(C3))

#define MMA8_F16(D0,D1,D2,D3, A0,A1, B0, C0,C1,C2,C3) \
  asm("mma.sync.aligned.m16n8k8.row.col.f32.f16.f16.f32 " \
      "{%0,%1,%2,%3}, {%4,%5}, {%6}, {%7,%8,%9,%10};" \
      : "=f"(D0),"=f"(D1),"=f"(D2),"=f"(D3) \
      : "r"(A0),"r"(A1), "r"(B0), \
        "f"(C0),"f"(C1),"f"(C2),"f"(C3))

__global__ void __launch_bounds__(TPB, 1) qtb_kernel(
    const float* __restrict__ x, const float* __restrict__ theta, const float* __restrict__ phi,
    const float* __restrict__ W1, const float* __restrict__ b1,
    const float* __restrict__ W2, const float* __restrict__ b2,
    const float* __restrict__ g1, const float* __restrict__ be1,
    const float* __restrict__ g2, const float* __restrict__ be2,
    float* __restrict__ out)
{
    extern __shared__ float smem[];
    const int tid = threadIdx.x;
    uint32_t* pW1h = (uint32_t*)(smem + W1H_OFF);
    uint32_t* pW1l = (uint32_t*)(smem + W1L_OFF);
    uint32_t* pW2  = (uint32_t*)(smem + W2_OFF);

    // ================= preamble: weight tables in mma-fragment layout =================
    for (int i = tid; i < 8192; i += TPB) {
        int c = i >> 5, r = i & 31, gq = r >> 2, tq = r & 3;
        int f = c * 8 + gq;
        float w0 = W1[f * 8 + 2 * tq];
        float w1 = W1[f * 8 + 2 * tq + 1];
        float h0 = rnd16(w0), h1 = rnd16(w1);
        pW1h[i] = pack_f16x2(h0, h1);
        pW1l[i] = pack_f16x2(w0 - h0, w1 - h1);
    }
    for (int i = tid; i < 8192; i += TPB) {
        int c = i >> 5, r = i & 31, gq = r >> 2, tq = r & 3;
        int f0 = c * 8 + 2 * tq;
        pW2[i] = pack_f16x2(W2[gq * 2048 + f0], W2[gq * 2048 + f0 + 1]);
    }
    for (int i = tid; i < 1024; i += TPB) {
        int c = i >> 2, tq = i & 3;
        ((float2*)(smem + BIAS_OFF))[i] = make_float2(b1[c * 8 + 2 * tq], b1[c * 8 + 2 * tq + 1]);
    }
    __syncthreads();

    const int wid  = tid >> 5, lane = tid & 31;
    const int g    = lane >> 2, t = lane & 3;

    // balanced tile map: block owns tiles [b*28, b*28+28)
    const int base = blockIdx.x * TPB_TILES;
    const int  t0v = base + wid;
    const int  t1v = base + 16 + wid;
    const bool a0  = t0v < NTILES;
    const bool a1  = (wid < 12) && (t1v < NTILES);
    const int tau0 = a0 ? t0v : 0;
    const int tau1 = a1 ? t1v : tau0;

    // ================= front: closed-form attn + LN1 + ffn_quantum =================
    const int lh = lane >> 4, ll = lane & 15;
    const int tok = (lh ? tau1 : tau0) * 16 + ll;

    float h[8];
    {
        float th_[8], cph[8], gg_[8], bb_[8];
        #pragma unroll
        for (int j = 0; j < 8; j++) {
            th_[j] = __ldg(theta + j);
            cph[j] = cosf(__ldg(phi + j));
            gg_[j] = __ldg(g1 + j);
            bb_[j] = __ldg(be1 + j);
        }
        const float* xp = x + (size_t)tok * 8;
        float4 a4 = __ldg((const float4*)xp);
        float4 b4 = __ldg((const float4*)(xp + 4));
        float xv[8] = {a4.x, a4.y, a4.z, a4.w, b4.x, b4.y, b4.z, b4.w};

        float c_[8];
        #pragma unroll
        for (int j = 0; j < 8; j++) c_[j] = cosf(xv[j] + th_[j]);
        float attn[8];
        float pr = c_[0];
        #pragma unroll
        for (int j = 1; j < 8; j++) { pr *= c_[j]; attn[j] = pr; }
        float qr = c_[1];
        #pragma unroll
        for (int j = 2; j < 8; j++) qr *= c_[j];
        attn[0] = qr;

        float y[8]; float s = 0.f;
        #pragma unroll
        for (int j = 0; j < 8; j++) { y[j] = xv[j] + attn[j]; s += y[j]; }
        float m = s * 0.125f, v = 0.f;
        #pragma unroll
        for (int j = 0; j < 8; j++) { float d = y[j] - m; v += d * d; }
        float inv = rsqrtf(v * 0.125f + 1e-5f);

        float* sz = smem + SZ_OFF + wid * 256 + lh * 128 + ll * 8;
        #pragma unroll
        for (int j = 0; j < 8; j++) {
            h[j] = (y[j] - m) * inv * gg_[j] + bb_[j];
            sz[j] = cph[j] * cosf(h[j]);            // z
        }
    }
    __syncwarp();

    // ================= A-frags for GEMM1 (hi/lo fp16 split) =================
    const float* z0 = smem + SZ_OFF + wid * 256;
    const float* z1 = z0 + 128;
    uint32_t A0h_g, A0h_G, A0l_g, A0l_G;
    uint32_t A1h_g, A1h_G, A1l_g, A1l_G;
    {
        int i0 = g * 8 + 2 * t, i1 = i0 + 1;
        int I0 = (g + 8) * 8 + 2 * t, I1 = I0 + 1;
        float a, b, ha, hb;
        a = z0[i0]; b = z0[i1]; ha = rnd16(a); hb = rnd16(b);
        A0h_g = pack_f16x2(ha, hb); A0l_g = pack_f16x2(a - ha, b - hb);
        a = z0[I0]; b = z0[I1]; ha = rnd16(a); hb = rnd16(b);
        A0h_G = pack_f16x2(ha, hb); A0l_G = pack_f16x2(a - ha, b - hb);
        a = z1[i0]; b = z1[i1]; ha = rnd16(a); hb = rnd16(b);
        A1h_g = pack_f16x2(ha, hb); A1l_g = pack_f16x2(a - ha, b - hb);
        a = z1[I0]; b = z1[I1]; ha = rnd16(a); hb = rnd16(b);
        A1h_G = pack_f16x2(ha, hb); A1l_G = pack_f16x2(a - ha, b - hb);
    }
    __syncwarp();   // sZ now reusable as epilogue scratch

    // ================= chunk loop =================
    float acc0[2][4] = {{0,0,0,0},{0,0,0,0}};
    float acc1[2][4] = {{0,0,0,0},{0,0,0,0}};
    const float2* pBia = (const float2*)(smem + BIAS_OFF);

    if (a1) {
        // two-tile loop
        #pragma unroll 4
        for (int c = 0; c < 256; c++) {
            uint32_t bWh = pW1h[(c << 5) + lane];
            uint32_t bWl = pW1l[(c << 5) + lane];
            uint32_t bW2 = pW2 [(c << 5) + lane];
            float2   bia = pBia[(c << 2) + t];
            const int s = c & 1;

            float e0,e1,e2,e3, f0,f1,f2,f3;
            // tile 0: hi and lo MMAs independent, merged by FADD
            MMA16_F16(e0,e1,e2,e3, A0h_g,A0h_G,A0l_g,A0l_G, bWh,bWh, bia.x,bia.y,bia.x,bia.y);
            MMA16_F16(f0,f1,f2,f3, A0h_g,A0h_G,A0l_g,A0l_G, bWl,bWl, 0.f,0.f,0.f,0.f);
            uint32_t p0 = hmax2z(pack_f16x2(e0 + f0, e1 + f1));
            uint32_t p1 = hmax2z(pack_f16x2(e2 + f2, e3 + f3));
            MMA8_F16(acc0[s][0],acc0[s][1],acc0[s][2],acc0[s][3], p0,p1, bW2,
                     acc0[s][0],acc0[s][1],acc0[s][2],acc0[s][3]);

            // tile 1
            MMA16_F16(e0,e1,e2,e3, A1h_g,A1h_G,A1l_g,A1l_G, bWh,bWh, bia.x,bia.y,bia.x,bia.y);
            MMA16_F16(f0,f1,f2,f3, A1h_g,A1h_G,A1l_g,A1l_G, bWl,bWl, 0.f,0.f,0.f,0.f);
            p0 = hmax2z(pack_f16x2(e0 + f0, e1 + f1));
            p1 = hmax2z(pack_f16x2(e2 + f2, e3 + f3));
            MMA8_F16(acc1[s][0],acc1[s][1],acc1[s][2],acc1[s][3], p0,p1, bW2,
                     acc1[s][0],acc1[s][1],acc1[s][2],acc1[s][3]);
        }
    } else if (a0) {
        // single-tile loop (half the MMA work)
        #pragma unroll 4
        for (int c = 0; c < 256; c++) {
            uint32_t bWh = pW1h[(c << 5) + lane];
            uint32_t bWl = pW1l[(c << 5) + lane];
            uint32_t bW2 = pW2 [(c << 5) + lane];
            float2   bia = pBia[(c << 2) + t];
            const int s = c & 1;

            float e0,e1,e2,e3, f0,f1,f2,f3;
            MMA16_F16(e0,e1,e2,e3, A0h_g,A0h_G,A0l_g,A0l_G, bWh,bWh, bia.x,bia.y,bia.x,bia.y);
            MMA16_F16(f0,f1,f2,f3, A0h_g,A0h_G,A0l_g,A0l_G, bWl,bWl, 0.f,0.f,0.f,0.f);
            uint32_t p0 = hmax2z(pack_f16x2(e0 + f0, e1 + f1));
            uint32_t p1 = hmax2z(pack_f16x2(e2 + f2, e3 + f3));
            MMA8_F16(acc0[s][0],acc0[s][1],acc0[s][2],acc0[s][3], p0,p1, bW2,
                     acc0[s][0],acc0[s][1],acc0[s][2],acc0[s][3]);
        }
    }

    // ================= epilogue: per-token residual + b2 + LN2 =================
    float* sE0 = smem + SZ_OFF + wid * 256;
    float* sE1 = sE0 + 128;
    sE0[g*8 + 2*t]       = acc0[0][0] + acc0[1][0];
    sE0[g*8 + 2*t + 1]   = acc0[0][1] + acc0[1][1];
    sE0[(g+8)*8 + 2*t]   = acc0[0][2] + acc0[1][2];
    sE0[(g+8)*8 + 2*t+1] = acc0[0][3] + acc0[1][3];
    sE1[g*8 + 2*t]       = acc1[0][0] + acc1[1][0];
    sE1[g*8 + 2*t + 1]   = acc1[0][1] + acc1[1][1];
    sE1[(g+8)*8 + 2*t]   = acc1[0][2] + acc1[1][2];
    sE1[(g+8)*8 + 2*t+1] = acc1[0][3] + acc1[1][3];
    __syncwarp();

    if (lh ? a1 : a0) {
        const float* sE = lh ? sE1 : sE0;
        float w[8]; float s2 = 0.f;
        #pragma unroll
        for (int e = 0; e < 8; e++) {
            w[e] = h[e] + sE[ll*8 + e] + __ldg(b2 + e);
            s2 += w[e];
        }
        float m2 = s2 * 0.125f, v2 = 0.f;
        #pragma unroll
        for (int e = 0; e < 8; e++) { float d = w[e] - m2; v2 += d * d; }
        float inv2 = rsqrtf(v2 * 0.125f + 1e-5f);
        float o[8];
        #pragma unroll
        for (int e = 0; e < 8; e++)
            o[e] = (w[e] - m2) * inv2 * __ldg(g2 + e) + __ldg(be2 + e);
        float* op = out + (size_t)tok * 8;
        *(float4*)op       = make_float4(o[0], o[1], o[2], o[3]);
        *(float4*)(op + 4) = make_float4(o[4], o[5], o[6], o[7]);
    }
}

extern "C" void kernel_launch(void* const* d_in, const int* in_sizes, int n_in,
                              void* d_out, int out_size) {
    const float* x      = (const float*)d_in[0];
    const float* theta  = (const float*)d_in[1];
    const float* phi    = (const float*)d_in[2];
    const float* W1     = (const float*)d_in[3];
    const float* b1     = (const float*)d_in[4];
    const float* W2     = (const float*)d_in[5];
    const float* b2     = (const float*)d_in[6];
    const float* gamma1 = (const float*)d_in[7];
    const float* beta1  = (const float*)d_in[8];
    const float* gamma2 = (const float*)d_in[9];
    const float* beta2  = (const float*)d_in[10];
    float* out = (float*)d_out;

    cudaFuncSetAttribute(qtb_kernel, cudaFuncAttributeMaxDynamicSharedMemorySize, SMEM_BYTES);
    qtb_kernel<<<GRID, TPB, SMEM_BYTES>>>(x, theta, phi, W1, b1, W2, b2,
                                          gamma1, beta1, gamma2, beta2, out);
}

// round 9
// speedup vs baseline: 2.4639x; 1.0065x over previous
#include <cuda_runtime.h>
#include <cuda_fp16.h>
#include <math.h>
#include <stdint.h>

// QuantumTransformerBlock — closed-form quantum ops + fp16 split-precision tensor-core FFN.
// One 16-token tile per warp, 32 warps/block, 148 blocks (tile = b*28 + w, w<28).
// GEMM1: 2x independent mma.m16n8k16.f16 (hi/lo) merged by FADD; GEMM2: mma.m16n8k8.f16
// with dual accumulators (even/odd c).

#define TPB   1024
#define NWARP 32
#define GRID  148
#define NTILES 4096
#define TILES_PER_BLOCK 28

// smem float offsets
#define W1H_OFF  0        // 8192 u32: [256 c][32 lane] f16x2 (W1 hi pair)
#define W1L_OFF  8192     // 8192 u32: W1 lo pair
#define W2_OFF   16384    // 8192 u32: [256 c][32 lane] f16x2 (W2, pi-permuted rows)
#define BIAS_OFF 24576    // 2048 floats: [256 c][4 t] float2 (b1 col pairs, fp32)
#define SZ_OFF   26624    // 4096 floats: [32 warp][16 tok][8 j] (reused as epi scratch)
#define SMEM_FLOATS (SZ_OFF + NWARP * 128)
#define SMEM_BYTES (SMEM_FLOATS * 4)       // 122880

__device__ __forceinline__ uint32_t pack_f16x2(float lo, float hi) {
    uint32_t d; asm("cvt.rn.f16x2.f32 %0, %1, %2;" : "=r"(d) : "f"(hi), "f"(lo)); return d;
}
__device__ __forceinline__ uint32_t hmax2z(uint32_t a) {
    uint32_t d; asm("max.f16x2 %0, %1, %2;" : "=r"(d) : "r"(a), "r"(0u)); return d;
}
__device__ __forceinline__ float rnd16(float v) {
    return __half2float(__float2half_rn(v));
}

#define MMA16_F16(D0,D1,D2,D3, A0,A1,A2,A3, B0,B1, C0,C1,C2,C3) \
  asm("mma.sync.aligned.m16n8k16.row.col.f32.f16.f16.f32 " \
      "{%0,%1,%2,%3}, {%4,%5,%6,%7}, {%8,%9}, {%10,%11,%12,%13};" \
      : "=f"(D0),"=f"(D1),"=f"(D2),"=f"(D3) \
      : "r"(A0),"r"(A1),"r"(A2),"r"(A3), "r"(B0),"r"(B1), \
        "f"(C0),"f"(C1),"f"(C2),"f"(C3))

#define MMA8_F16(D0,D1,D2,D3, A0,A1, B0, C0,C1,C2,C3) \
  asm("mma.sync.aligned.m16n8k8.row.col.f32.f16.f16.f32 " \
      "{%0,%1,%2,%3}, {%4,%5}, {%6}, {%7,%8,%9,%10};" \
      : "=f"(D0),"=f"(D1),"=f"(D2),"=f"(D3) \
      : "r"(A0),"r"(A1), "r"(B0), \
        "f"(C0),"f"(C1),"f"(C2),"f"(C3))

__global__ void __launch_bounds__(TPB, 1) qtb_kernel(
    const float* __restrict__ x, const float* __restrict__ theta, const float* __restrict__ phi,
    const float* __restrict__ W1, const float* __restrict__ b1,
    const float* __restrict__ W2, const float* __restrict__ b2,
    const float* __restrict__ g1, const float* __restrict__ be1,
    const float* __restrict__ g2, const float* __restrict__ be2,
    float* __restrict__ out)
{
    extern __shared__ float smem[];
    const int tid = threadIdx.x;
    uint32_t* pW1h = (uint32_t*)(smem + W1H_OFF);
    uint32_t* pW1l = (uint32_t*)(smem + W1L_OFF);
    uint32_t* pW2  = (uint32_t*)(smem + W2_OFF);

    // ================= preamble: weight tables in mma-fragment layout =================
    for (int i = tid; i < 8192; i += TPB) {
        int c = i >> 5, r = i & 31, gq = r >> 2, tq = r & 3;
        int f = c * 8 + gq;
        float w0 = W1[f * 8 + 2 * tq];
        float w1 = W1[f * 8 + 2 * tq + 1];
        float h0 = rnd16(w0), h1 = rnd16(w1);
        pW1h[i] = pack_f16x2(h0, h1);
        pW1l[i] = pack_f16x2(w0 - h0, w1 - h1);
    }
    for (int i = tid; i < 8192; i += TPB) {
        int c = i >> 5, r = i & 31, gq = r >> 2, tq = r & 3;
        int f0 = c * 8 + 2 * tq;
        pW2[i] = pack_f16x2(W2[gq * 2048 + f0], W2[gq * 2048 + f0 + 1]);
    }
    for (int i = tid; i < 1024; i += TPB) {
        int c = i >> 2, tq = i & 3;
        ((float2*)(smem + BIAS_OFF))[i] = make_float2(b1[c * 8 + 2 * tq], b1[c * 8 + 2 * tq + 1]);
    }
    __syncthreads();

    const int wid  = tid >> 5, lane = tid & 31;
    const int g    = lane >> 2, t = lane & 3;

    // one tile per warp: tile = b*28 + w for w < 28
    const int t0v = blockIdx.x * TILES_PER_BLOCK + wid;
    const bool a0 = (wid < TILES_PER_BLOCK) && (t0v < NTILES);
    const int tau = a0 ? t0v : 0;

    const int lh = lane >> 4, ll = lane & 15;
    const int tok = tau * 16 + ll;                 // lanes 16-31 duplicate (gated at writes)

    float h[8];
    if (a0) {
        // ================= front: closed-form attn + LN1 + ffn_quantum =================
        float th_[8], cph[8], gg_[8], bb_[8];
        #pragma unroll
        for (int j = 0; j < 8; j++) {
            th_[j] = __ldg(theta + j);
            cph[j] = cosf(__ldg(phi + j));
            gg_[j] = __ldg(g1 + j);
            bb_[j] = __ldg(be1 + j);
        }
        const float* xp = x + (size_t)tok * 8;
        float4 a4 = __ldg((const float4*)xp);
        float4 b4 = __ldg((const float4*)(xp + 4));
        float xv[8] = {a4.x, a4.y, a4.z, a4.w, b4.x, b4.y, b4.z, b4.w};

        float c_[8];
        #pragma unroll
        for (int j = 0; j < 8; j++) c_[j] = cosf(xv[j] + th_[j]);
        float attn[8];
        float pr = c_[0];
        #pragma unroll
        for (int j = 1; j < 8; j++) { pr *= c_[j]; attn[j] = pr; }
        float qr = c_[1];
        #pragma unroll
        for (int j = 2; j < 8; j++) qr *= c_[j];
        attn[0] = qr;

        float y[8]; float s = 0.f;
        #pragma unroll
        for (int j = 0; j < 8; j++) { y[j] = xv[j] + attn[j]; s += y[j]; }
        float m = s * 0.125f, v = 0.f;
        #pragma unroll
        for (int j = 0; j < 8; j++) { float d = y[j] - m; v += d * d; }
        float inv = rsqrtf(v * 0.125f + 1e-5f);

        float* sz = smem + SZ_OFF + wid * 128 + ll * 8;
        #pragma unroll
        for (int j = 0; j < 8; j++) {
            h[j] = (y[j] - m) * inv * gg_[j] + bb_[j];
            if (lh == 0) sz[j] = cph[j] * cosf(h[j]);   // z (lanes 0-15 write)
        }
    }
    __syncwarp();

    // ================= A-frags for GEMM1 (hi/lo fp16 split) =================
    const float* z0 = smem + SZ_OFF + wid * 128;
    uint32_t Ah_g, Ah_G, Al_g, Al_G;
    {
        int i0 = g * 8 + 2 * t, i1 = i0 + 1;
        int I0 = (g + 8) * 8 + 2 * t, I1 = I0 + 1;
        float a = z0[i0], b = z0[i1];
        float ha = rnd16(a), hb = rnd16(b);
        Ah_g = pack_f16x2(ha, hb); Al_g = pack_f16x2(a - ha, b - hb);
        a = z0[I0]; b = z0[I1]; ha = rnd16(a); hb = rnd16(b);
        Ah_G = pack_f16x2(ha, hb); Al_G = pack_f16x2(a - ha, b - hb);
    }
    __syncwarp();   // sZ now reusable as epilogue scratch

    // ================= chunk loop: 256 chunks of 8 f =================
    float acc[2][4] = {{0,0,0,0},{0,0,0,0}};
    const float2* pBia = (const float2*)(smem + BIAS_OFF);

    if (a0) {
        #pragma unroll 4
        for (int c = 0; c < 256; c++) {
            uint32_t bWh = pW1h[(c << 5) + lane];
            uint32_t bWl = pW1l[(c << 5) + lane];
            uint32_t bW2 = pW2 [(c << 5) + lane];
            float2   bia = pBia[(c << 2) + t];
            const int s = c & 1;

            float e0,e1,e2,e3, f0,f1,f2,f3;
            MMA16_F16(e0,e1,e2,e3, Ah_g,Ah_G,Al_g,Al_G, bWh,bWh, bia.x,bia.y,bia.x,bia.y);
            MMA16_F16(f0,f1,f2,f3, Ah_g,Ah_G,Al_g,Al_G, bWl,bWl, 0.f,0.f,0.f,0.f);
            uint32_t p0 = hmax2z(pack_f16x2(e0 + f0, e1 + f1));
            uint32_t p1 = hmax2z(pack_f16x2(e2 + f2, e3 + f3));
            MMA8_F16(acc[s][0],acc[s][1],acc[s][2],acc[s][3], p0,p1, bW2,
                     acc[s][0],acc[s][1],acc[s][2],acc[s][3]);
        }
    }

    // ================= epilogue: per-token residual + b2 + LN2 =================
    float* sE = smem + SZ_OFF + wid * 128;
    sE[g*8 + 2*t]       = acc[0][0] + acc[1][0];
    sE[g*8 + 2*t + 1]   = acc[0][1] + acc[1][1];
    sE[(g+8)*8 + 2*t]   = acc[0][2] + acc[1][2];
    sE[(g+8)*8 + 2*t+1] = acc[0][3] + acc[1][3];
    __syncwarp();

    if (a0 && lh == 0) {
        float w[8]; float s2 = 0.f;
        #pragma unroll
        for (int e = 0; e < 8; e++) {
            w[e] = h[e] + sE[ll*8 + e] + __ldg(b2 + e);
            s2 += w[e];
        }
        float m2 = s2 * 0.125f, v2 = 0.f;
        #pragma unroll
        for (int e = 0; e < 8; e++) { float d = w[e] - m2; v2 += d * d; }
        float inv2 = rsqrtf(v2 * 0.125f + 1e-5f);
        float o[8];
        #pragma unroll
        for (int e = 0; e < 8; e++)
            o[e] = (w[e] - m2) * inv2 * __ldg(g2 + e) + __ldg(be2 + e);
        float* op = out + (size_t)tok * 8;
        *(float4*)op       = make_float4(o[0], o[1], o[2], o[3]);
        *(float4*)(op + 4) = make_float4(o[4], o[5], o[6], o[7]);
    }
}

extern "C" void kernel_launch(void* const* d_in, const int* in_sizes, int n_in,
                              void* d_out, int out_size) {
    const float* x      = (const float*)d_in[0];
    const float* theta  = (const float*)d_in[1];
    const float* phi    = (const float*)d_in[2];
    const float* W1     = (const float*)d_in[3];
    const float* b1     = (const float*)d_in[4];
    const float* W2     = (const float*)d_in[5];
    const float* b2     = (const float*)d_in[6];
    const float* gamma1 = (const float*)d_in[7];
    const float* beta1  = (const float*)d_in[8];
    const float* gamma2 = (const float*)d_in[9];
    const float* beta2  = (const float*)d_in[10];
    float* out = (float*)d_out;

    cudaFuncSetAttribute(qtb_kernel, cudaFuncAttributeMaxDynamicSharedMemorySize, SMEM_BYTES);
    qtb_kernel<<<GRID, TPB, SMEM_BYTES>>>(x, theta, phi, W1, b1, W2, b2,
                                          gamma1, beta1, gamma2, beta2, out);
}

// round 10
// speedup vs baseline: 3.9244x; 1.5927x over previous
#include <cuda_runtime.h>
#include <cuda_fp16.h>
#include <math.h>
#include <stdint.h>

// QuantumTransformerBlock — closed-form quantum ops + lean fp16 tensor-core FFN.
// GEMM1: single mma.m16n8k8.f16 per chunk (fp16 z & W1, fp32 bias in C).
// GEMM2: chunk-paired mma.m16n8k16.f16 (virtual K=16 over two 8-f chunks, pi-permuted W2).
// One 16-token tile per warp, 32 warps/block, 148 blocks (tile = b*28 + w, w<28).

#define TPB   1024
#define NWARP 32
#define GRID  148
#define NTILES 4096
#define TILES_PER_BLOCK 28

// smem float offsets
#define W1_OFF   0        // 8192 u32: [128 cp][32 lane][2 half] f16x2 W1 frag words
#define W2_OFF   8192     // 8192 u32: same indexing, W2 (pi-permuted rows)
#define BIAS_OFF 16384    // 2048 floats: [128 cp][4 t] float4 (b1 cols 2t,2t+1 of c0 then c1)
#define SZ_OFF   18432    // 4096 floats: [32 warp][16 tok][8 j] (reused as epi scratch)
#define SMEM_FLOATS (SZ_OFF + NWARP * 128)
#define SMEM_BYTES (SMEM_FLOATS * 4)       // 90112

__device__ __forceinline__ uint32_t pack_f16x2(float lo, float hi) {
    uint32_t d; asm("cvt.rn.f16x2.f32 %0, %1, %2;" : "=r"(d) : "f"(hi), "f"(lo)); return d;
}
__device__ __forceinline__ uint32_t hmax2z(uint32_t a) {
    uint32_t d; asm("max.f16x2 %0, %1, %2;" : "=r"(d) : "r"(a), "r"(0u)); return d;
}

#define MMA16_F16(D0,D1,D2,D3, A0,A1,A2,A3, B0,B1, C0,C1,C2,C3) \
  asm("mma.sync.aligned.m16n8k16.row.col.f32.f16.f16.f32 " \
      "{%0,%1,%2,%3}, {%4,%5,%6,%7}, {%8,%9}, {%10,%11,%12,%13};" \
      : "=f"(D0),"=f"(D1),"=f"(D2),"=f"(D3) \
      : "r"(A0),"r"(A1),"r"(A2),"r"(A3), "r"(B0),"r"(B1), \
        "f"(C0),"f"(C1),"f"(C2),"f"(C3))

#define MMA8_F16(D0,D1,D2,D3, A0,A1, B0, C0,C1,C2,C3) \
  asm("mma.sync.aligned.m16n8k8.row.col.f32.f16.f16.f32 " \
      "{%0,%1,%2,%3}, {%4,%5}, {%6}, {%7,%8,%9,%10};" \
      : "=f"(D0),"=f"(D1),"=f"(D2),"=f"(D3) \
      : "r"(A0),"r"(A1), "r"(B0), \
        "f"(C0),"f"(C1),"f"(C2),"f"(C3))

__global__ void __launch_bounds__(TPB, 1) qtb_kernel(
    const float* __restrict__ x, const float* __restrict__ theta, const float* __restrict__ phi,
    const float* __restrict__ W1, const float* __restrict__ b1,
    const float* __restrict__ W2, const float* __restrict__ b2,
    const float* __restrict__ g1, const float* __restrict__ be1,
    const float* __restrict__ g2, const float* __restrict__ be2,
    float* __restrict__ out)
{
    extern __shared__ float smem[];
    const int tid = threadIdx.x;
    uint32_t* pW1 = (uint32_t*)(smem + W1_OFF);
    uint32_t* pW2 = (uint32_t*)(smem + W2_OFF);

    // ================= preamble: weight tables in mma-fragment layout =================
    // u32 index = cp*64 + lane*2 + (c&1); lane = (g<<2)|t.
    for (int i = tid; i < 8192; i += TPB) {
        int cp = i >> 6, lane_ = (i >> 1) & 31, hf = i & 1;
        int c = cp * 2 + hf;
        int gq = lane_ >> 2, tq = lane_ & 3;
        int f = c * 8 + gq;
        pW1[i] = pack_f16x2(W1[f * 8 + 2 * tq], W1[f * 8 + 2 * tq + 1]);
    }
    for (int i = tid; i < 8192; i += TPB) {
        int cp = i >> 6, lane_ = (i >> 1) & 31, hf = i & 1;
        int c = cp * 2 + hf;
        int gq = lane_ >> 2, tq = lane_ & 3;
        int f0 = c * 8 + 2 * tq;
        pW2[i] = pack_f16x2(W2[gq * 2048 + f0], W2[gq * 2048 + f0 + 1]);
    }
    // bias float4 per (cp, t): (b1[c0*8+2t], b1[c0*8+2t+1], b1[c1*8+2t], b1[c1*8+2t+1])
    for (int i = tid; i < 512; i += TPB) {
        int cp = i >> 2, tq = i & 3;
        int c0 = cp * 2, c1 = c0 + 1;
        ((float4*)(smem + BIAS_OFF))[i] = make_float4(
            b1[c0 * 8 + 2 * tq], b1[c0 * 8 + 2 * tq + 1],
            b1[c1 * 8 + 2 * tq], b1[c1 * 8 + 2 * tq + 1]);
    }
    __syncthreads();

    const int wid  = tid >> 5, lane = tid & 31;
    const int g    = lane >> 2, t = lane & 3;

    // one tile per warp: tile = b*28 + w for w < 28
    const int t0v = blockIdx.x * TILES_PER_BLOCK + wid;
    const bool a0 = (wid < TILES_PER_BLOCK) && (t0v < NTILES);
    const int tau = a0 ? t0v : 0;

    const int lh = lane >> 4, ll = lane & 15;
    const int tok = tau * 16 + ll;                 // lanes 16-31 duplicate (gated at writes)

    float h[8];
    if (a0) {
        // ================= front: closed-form attn + LN1 + ffn_quantum =================
        float th_[8], cph[8], gg_[8], bb_[8];
        #pragma unroll
        for (int j = 0; j < 8; j++) {
            th_[j] = __ldg(theta + j);
            cph[j] = cosf(__ldg(phi + j));
            gg_[j] = __ldg(g1 + j);
            bb_[j] = __ldg(be1 + j);
        }
        const float* xp = x + (size_t)tok * 8;
        float4 a4 = __ldg((const float4*)xp);
        float4 b4 = __ldg((const float4*)(xp + 4));
        float xv[8] = {a4.x, a4.y, a4.z, a4.w, b4.x, b4.y, b4.z, b4.w};

        float c_[8];
        #pragma unroll
        for (int j = 0; j < 8; j++) c_[j] = cosf(xv[j] + th_[j]);
        float attn[8];
        float pr = c_[0];
        #pragma unroll
        for (int j = 1; j < 8; j++) { pr *= c_[j]; attn[j] = pr; }
        float qr = c_[1];
        #pragma unroll
        for (int j = 2; j < 8; j++) qr *= c_[j];
        attn[0] = qr;

        float y[8]; float s = 0.f;
        #pragma unroll
        for (int j = 0; j < 8; j++) { y[j] = xv[j] + attn[j]; s += y[j]; }
        float m = s * 0.125f, v = 0.f;
        #pragma unroll
        for (int j = 0; j < 8; j++) { float d = y[j] - m; v += d * d; }
        float inv = rsqrtf(v * 0.125f + 1e-5f);

        float* sz = smem + SZ_OFF + wid * 128 + ll * 8;
        #pragma unroll
        for (int j = 0; j < 8; j++) {
            h[j] = (y[j] - m) * inv * gg_[j] + bb_[j];
            if (lh == 0) sz[j] = cph[j] * cosf(h[j]);   // z (lanes 0-15 write)
        }
    }
    __syncwarp();

    // ================= A-frag for GEMM1 (plain fp16 z) =================
    const float* z0 = smem + SZ_OFF + wid * 128;
    uint32_t Az_g, Az_G;
    {
        int i0 = g * 8 + 2 * t;
        int I0 = (g + 8) * 8 + 2 * t;
        Az_g = pack_f16x2(z0[i0], z0[i0 + 1]);
        Az_G = pack_f16x2(z0[I0], z0[I0 + 1]);
    }
    __syncwarp();   // sZ now reusable as epilogue scratch

    // ================= chunk-pair loop: 128 iterations of 16 f =================
    float acc[2][4] = {{0,0,0,0},{0,0,0,0}};
    const uint2*  q1  = (const uint2*)pW1;
    const uint2*  q2  = (const uint2*)pW2;
    const float4* pB4 = (const float4*)(smem + BIAS_OFF);

    if (a0) {
        #pragma unroll 4
        for (int cp = 0; cp < 128; cp++) {
            uint2  w1p = q1[(cp << 5) + lane];     // (chunk c0 word, chunk c1 word)
            uint2  w2p = q2[(cp << 5) + lane];
            float4 bia = pB4[(cp << 2) + t];
            const int s = cp & 1;

            float e0,e1,e2,e3, f0,f1,f2,f3;
            MMA8_F16(e0,e1,e2,e3, Az_g,Az_G, w1p.x, bia.x,bia.y,bia.x,bia.y);   // chunk c0
            MMA8_F16(f0,f1,f2,f3, Az_g,Az_G, w1p.y, bia.z,bia.w,bia.z,bia.w);   // chunk c1
            uint32_t p00 = hmax2z(pack_f16x2(e0, e1));
            uint32_t p01 = hmax2z(pack_f16x2(e2, e3));
            uint32_t p10 = hmax2z(pack_f16x2(f0, f1));
            uint32_t p11 = hmax2z(pack_f16x2(f2, f3));
            // GEMM2 over virtual K=16 = [c0 | c1]
            MMA16_F16(acc[s][0],acc[s][1],acc[s][2],acc[s][3],
                      p00,p01,p10,p11, w2p.x,w2p.y,
                      acc[s][0],acc[s][1],acc[s][2],acc[s][3]);
        }
    }

    // ================= epilogue: per-token residual + b2 + LN2 =================
    float* sE = smem + SZ_OFF + wid * 128;
    sE[g*8 + 2*t]       = acc[0][0] + acc[1][0];
    sE[g*8 + 2*t + 1]   = acc[0][1] + acc[1][1];
    sE[(g+8)*8 + 2*t]   = acc[0][2] + acc[1][2];
    sE[(g+8)*8 + 2*t+1] = acc[0][3] + acc[1][3];
    __syncwarp();

    if (a0 && lh == 0) {
        float w[8]; float s2 = 0.f;
        #pragma unroll
        for (int e = 0; e < 8; e++) {
            w[e] = h[e] + sE[ll*8 + e] + __ldg(b2 + e);
            s2 += w[e];
        }
        float m2 = s2 * 0.125f, v2 = 0.f;
        #pragma unroll
        for (int e = 0; e < 8; e++) { float d = w[e] - m2; v2 += d * d; }
        float inv2 = rsqrtf(v2 * 0.125f + 1e-5f);
        float o[8];
        #pragma unroll
        for (int e = 0; e < 8; e++)
            o[e] = (w[e] - m2) * inv2 * __ldg(g2 + e) + __ldg(be2 + e);
        float* op = out + (size_t)tok * 8;
        *(float4*)op       = make_float4(o[0], o[1], o[2], o[3]);
        *(float4*)(op + 4) = make_float4(o[4], o[5], o[6], o[7]);
    }
}

extern "C" void kernel_launch(void* const* d_in, const int* in_sizes, int n_in,
                              void* d_out, int out_size) {
    const float* x      = (const float*)d_in[0];
    const float* theta  = (const float*)d_in[1];
    const float* phi    = (const float*)d_in[2];
    const float* W1     = (const float*)d_in[3];
    const float* b1     = (const float*)d_in[4];
    const float* W2     = (const float*)d_in[5];
    const float* b2     = (const float*)d_in[6];
    const float* gamma1 = (const float*)d_in[7];
    const float* beta1  = (const float*)d_in[8];
    const float* gamma2 = (const float*)d_in[9];
    const float* beta2  = (const float*)d_in[10];
    float* out = (float*)d_out;

    cudaFuncSetAttribute(qtb_kernel, cudaFuncAttributeMaxDynamicSharedMemorySize, SMEM_BYTES);
    qtb_kernel<<<GRID, TPB, SMEM_BYTES>>>(x, theta, phi, W1, b1, W2, b2,
                                          gamma1, beta1, gamma2, beta2, out);
}

// round 11
// speedup vs baseline: 3.9407x; 1.0042x over previous
#include <cuda_runtime.h>
#include <cuda_fp16.h>
#include <math.h>
#include <stdint.h>

// QuantumTransformerBlock — closed-form quantum ops + lean fp16 tensor-core FFN.
// GEMM1: mma.m16n8k8.f16 per chunk (fp32 bias via C operand).
// GEMM2: chunk-paired mma.m16n8k16.f16 (virtual K=16, pi-permuted W2 rows).
// One 16-token tile per warp, 32 warps/block, 148 blocks.
// R11: fused uint4 weight table (1 LDS.128 for W1c0/W1c1/W2c0/W2c1), h stashed in smem
// across the loop to relieve the 64-reg/thread cap.

#define TPB   1024
#define NWARP 32
#define GRID  148
#define NTILES 4096
#define TILES_PER_BLOCK 28

// smem float offsets
#define WB_OFF   0        // 16384 u32 as uint4[4096]: [128 cp][32 lane] (w1c0,w1c1,w2c0,w2c1)
#define BIAS_OFF 16384    // 2048 floats: [128 cp][4 t] float4 (b1 cols 2t,2t+1 of c0 then c1)
#define SZ_OFF   18432    // 4096 floats: [32 warp][16 tok][8 j]  z, later epi scratch
#define H_OFF    22528    // 4096 floats: [32 warp][16 tok][8 j]  h stash (persists over loop)
#define SMEM_FLOATS (H_OFF + NWARP * 128)
#define SMEM_BYTES (SMEM_FLOATS * 4)       // 106496

__device__ __forceinline__ uint32_t pack_f16x2(float lo, float hi) {
    uint32_t d; asm("cvt.rn.f16x2.f32 %0, %1, %2;" : "=r"(d) : "f"(hi), "f"(lo)); return d;
}
__device__ __forceinline__ uint32_t hmax2z(uint32_t a) {
    uint32_t d; asm("max.f16x2 %0, %1, %2;" : "=r"(d) : "r"(a), "r"(0u)); return d;
}

#define MMA16_F16(D0,D1,D2,D3, A0,A1,A2,A3, B0,B1, C0,C1,C2,C3) \
  asm("mma.sync.aligned.m16n8k16.row.col.f32.f16.f16.f32 " \
      "{%0,%1,%2,%3}, {%4,%5,%6,%7}, {%8,%9}, {%10,%11,%12,%13};" \
      : "=f"(D0),"=f"(D1),"=f"(D2),"=f"(D3) \
      : "r"(A0),"r"(A1),"r"(A2),"r"(A3), "r"(B0),"r"(B1), \
        "f"(C0),"f"(C1),"f"(C2),"f"(C3))

#define MMA8_F16(D0,D1,D2,D3, A0,A1, B0, C0,C1,C2,C3) \
  asm("mma.sync.aligned.m16n8k8.row.col.f32.f16.f16.f32 " \
      "{%0,%1,%2,%3}, {%4,%5}, {%6}, {%7,%8,%9,%10};" \
      : "=f"(D0),"=f"(D1),"=f"(D2),"=f"(D3) \
      : "r"(A0),"r"(A1), "r"(B0), \
        "f"(C0),"f"(C1),"f"(C2),"f"(C3))

__global__ void __launch_bounds__(TPB, 1) qtb_kernel(
    const float* __restrict__ x, const float* __restrict__ theta, const float* __restrict__ phi,
    const float* __restrict__ W1, const float* __restrict__ b1,
    const float* __restrict__ W2, const float* __restrict__ b2,
    const float* __restrict__ g1, const float* __restrict__ be1,
    const float* __restrict__ g2, const float* __restrict__ be2,
    float* __restrict__ out)
{
    extern __shared__ float smem[];
    const int tid = threadIdx.x;
    uint4* pWB = (uint4*)(smem + WB_OFF);

    // ================= preamble: fused weight table in mma-fragment layout =================
    // entry (cp, lane=g*4+t): w1cX = (W1[f=cX*8+g][2t], [2t+1]); w2cX = (W2[g][cX*8+2t], [+1])
    for (int i = tid; i < 4096; i += TPB) {
        int cp = i >> 5, lane_ = i & 31;
        int gq = lane_ >> 2, tq = lane_ & 3;
        int c0 = cp * 2, c1 = c0 + 1;
        int f0 = c0 * 8 + gq, f1 = c1 * 8 + gq;
        uint4 v;
        v.x = pack_f16x2(W1[f0 * 8 + 2 * tq], W1[f0 * 8 + 2 * tq + 1]);
        v.y = pack_f16x2(W1[f1 * 8 + 2 * tq], W1[f1 * 8 + 2 * tq + 1]);
        v.z = pack_f16x2(W2[gq * 2048 + c0 * 8 + 2 * tq], W2[gq * 2048 + c0 * 8 + 2 * tq + 1]);
        v.w = pack_f16x2(W2[gq * 2048 + c1 * 8 + 2 * tq], W2[gq * 2048 + c1 * 8 + 2 * tq + 1]);
        pWB[i] = v;
    }
    // bias float4 per (cp, t)
    for (int i = tid; i < 512; i += TPB) {
        int cp = i >> 2, tq = i & 3;
        int c0 = cp * 2, c1 = c0 + 1;
        ((float4*)(smem + BIAS_OFF))[i] = make_float4(
            b1[c0 * 8 + 2 * tq], b1[c0 * 8 + 2 * tq + 1],
            b1[c1 * 8 + 2 * tq], b1[c1 * 8 + 2 * tq + 1]);
    }
    __syncthreads();

    const int wid  = tid >> 5, lane = tid & 31;
    const int g    = lane >> 2, t = lane & 3;

    const int t0v = blockIdx.x * TILES_PER_BLOCK + wid;
    const bool a0 = (wid < TILES_PER_BLOCK) && (t0v < NTILES);
    const int tau = a0 ? t0v : 0;

    const int lh = lane >> 4, ll = lane & 15;
    const int tok = tau * 16 + ll;                 // lanes 16-31 duplicate (gated at writes)

    if (a0) {
        // ================= front: closed-form attn + LN1 + ffn_quantum =================
        float th_[8], cph[8], gg_[8], bb_[8];
        #pragma unroll
        for (int j = 0; j < 8; j++) {
            th_[j] = __ldg(theta + j);
            cph[j] = cosf(__ldg(phi + j));
            gg_[j] = __ldg(g1 + j);
            bb_[j] = __ldg(be1 + j);
        }
        const float* xp = x + (size_t)tok * 8;
        float4 a4 = __ldg((const float4*)xp);
        float4 b4 = __ldg((const float4*)(xp + 4));
        float xv[8] = {a4.x, a4.y, a4.z, a4.w, b4.x, b4.y, b4.z, b4.w};

        float c_[8];
        #pragma unroll
        for (int j = 0; j < 8; j++) c_[j] = cosf(xv[j] + th_[j]);
        float attn[8];
        float pr = c_[0];
        #pragma unroll
        for (int j = 1; j < 8; j++) { pr *= c_[j]; attn[j] = pr; }
        float qr = c_[1];
        #pragma unroll
        for (int j = 2; j < 8; j++) qr *= c_[j];
        attn[0] = qr;

        float y[8]; float s = 0.f;
        #pragma unroll
        for (int j = 0; j < 8; j++) { y[j] = xv[j] + attn[j]; s += y[j]; }
        float m = s * 0.125f, v = 0.f;
        #pragma unroll
        for (int j = 0; j < 8; j++) { float d = y[j] - m; v += d * d; }
        float inv = rsqrtf(v * 0.125f + 1e-5f);

        float* sz = smem + SZ_OFF + wid * 128 + ll * 8;
        float* sh = smem + H_OFF  + wid * 128 + ll * 8;
        #pragma unroll
        for (int j = 0; j < 8; j++) {
            float hj = (y[j] - m) * inv * gg_[j] + bb_[j];
            if (lh == 0) {                          // lanes 0-15 own their token
                sh[j] = hj;                         // stash h for epilogue (frees regs)
                sz[j] = cph[j] * cosf(hj);          // z
            }
        }
    }
    __syncwarp();

    // ================= A-frag for GEMM1 (plain fp16 z) =================
    const float* z0 = smem + SZ_OFF + wid * 128;
    uint32_t Az_g, Az_G;
    {
        int i0 = g * 8 + 2 * t;
        int I0 = (g + 8) * 8 + 2 * t;
        Az_g = pack_f16x2(z0[i0], z0[i0 + 1]);
        Az_G = pack_f16x2(z0[I0], z0[I0 + 1]);
    }
    __syncwarp();   // sZ now reusable as epilogue scratch

    // ================= chunk-pair loop: 128 iterations of 16 f =================
    float acc[2][4] = {{0,0,0,0},{0,0,0,0}};
    const float4* pB4 = (const float4*)(smem + BIAS_OFF);

    if (a0) {
        #pragma unroll 8
        for (int cp = 0; cp < 128; cp++) {
            uint4  wq  = pWB[(cp << 5) + lane];    // (w1c0, w1c1, w2c0, w2c1)
            float4 bia = pB4[(cp << 2) + t];
            const int s = cp & 1;

            float e0,e1,e2,e3, f0,f1,f2,f3;
            MMA8_F16(e0,e1,e2,e3, Az_g,Az_G, wq.x, bia.x,bia.y,bia.x,bia.y);   // chunk c0
            MMA8_F16(f0,f1,f2,f3, Az_g,Az_G, wq.y, bia.z,bia.w,bia.z,bia.w);   // chunk c1
            uint32_t p00 = hmax2z(pack_f16x2(e0, e1));
            uint32_t p01 = hmax2z(pack_f16x2(e2, e3));
            uint32_t p10 = hmax2z(pack_f16x2(f0, f1));
            uint32_t p11 = hmax2z(pack_f16x2(f2, f3));
            MMA16_F16(acc[s][0],acc[s][1],acc[s][2],acc[s][3],
                      p00,p01,p10,p11, wq.z,wq.w,
                      acc[s][0],acc[s][1],acc[s][2],acc[s][3]);
        }
    }

    // ================= epilogue: per-token residual + b2 + LN2 =================
    float* sE = smem + SZ_OFF + wid * 128;
    sE[g*8 + 2*t]       = acc[0][0] + acc[1][0];
    sE[g*8 + 2*t + 1]   = acc[0][1] + acc[1][1];
    sE[(g+8)*8 + 2*t]   = acc[0][2] + acc[1][2];
    sE[(g+8)*8 + 2*t+1] = acc[0][3] + acc[1][3];
    __syncwarp();

    if (a0 && lh == 0) {
        const float* sh = smem + H_OFF + wid * 128 + ll * 8;
        float w[8]; float s2 = 0.f;
        #pragma unroll
        for (int e = 0; e < 8; e++) {
            w[e] = sh[e] + sE[ll*8 + e] + __ldg(b2 + e);
            s2 += w[e];
        }
        float m2 = s2 * 0.125f, v2 = 0.f;
        #pragma unroll
        for (int e = 0; e < 8; e++) { float d = w[e] - m2; v2 += d * d; }
        float inv2 = rsqrtf(v2 * 0.125f + 1e-5f);
        float o[8];
        #pragma unroll
        for (int e = 0; e < 8; e++)
            o[e] = (w[e] - m2) * inv2 * __ldg(g2 + e) + __ldg(be2 + e);
        float* op = out + (size_t)tok * 8;
        *(float4*)op       = make_float4(o[0], o[1], o[2], o[3]);
        *(float4*)(op + 4) = make_float4(o[4], o[5], o[6], o[7]);
    }
}

extern "C" void kernel_launch(void* const* d_in, const int* in_sizes, int n_in,
                              void* d_out, int out_size) {
    const float* x      = (const float*)d_in[0];
    const float* theta  = (const float*)d_in[1];
    const float* phi    = (const float*)d_in[2];
    const float* W1     = (const float*)d_in[3];
    const float* b1     = (const float*)d_in[4];
    const float* W2     = (const float*)d_in[5];
    const float* b2     = (const float*)d_in[6];
    const float* gamma1 = (const float*)d_in[7];
    const float* beta1  = (const float*)d_in[8];
    const float* gamma2 = (const float*)d_in[9];
    const float* beta2  = (const float*)d_in[10];
    float* out = (float*)d_out;

    cudaFuncSetAttribute(qtb_kernel, cudaFuncAttributeMaxDynamicSharedMemorySize, SMEM_BYTES);
    qtb_kernel<<<GRID, TPB, SMEM_BYTES>>>(x, theta, phi, W1, b1, W2, b2,
                                          gamma1, beta1, gamma2, beta2, out);
}

// round 12
// speedup vs baseline: 3.9572x; 1.0042x over previous
#include <cuda_runtime.h>
#include <cuda_fp16.h>
#include <math.h>
#include <stdint.h>

// QuantumTransformerBlock — closed-form quantum ops + fp16 tensor-core FFN, f-split warp pairs.
// Warp pair (2w, 2w+1) shares TWO 16-token tiles; each warp does half the f-range (64 chunk
// pairs), so each weight LDS.128 feeds two tiles' MMAs. GEMM1: mma.m16n8k8 with f16 output
// (D-regs are directly the GEMM2 A-frag; bias in f16 C). GEMM2: chunk-paired mma.m16n8k16,
// fp32 acc. Partial sums across the f-halves combined via smem + one __syncthreads.

#define TPB   1024
#define GRID  148
#define NTASKS 2048            // 4096 tiles / 2 tiles per task
#define PAIRS_PER_BLOCK 14     // 148*14 = 2072 >= 2048

// smem layout (floats)
#define WB_OFF   0        // 16384 u32 as uint4[4096]: [128 cp][32 lane] (w1c0,w1c1,w2c0,w2c1)
#define B16_OFF  16384    // 1024 u32 as uint2[512]: [128 cp][4 t] (bias f16x2 c0, c1)
#define SZ_OFF   17408    // 8192 floats: [32 warp][32 tok][8 j]  z, later partial-sum exchange
#define SMEM_FLOATS (SZ_OFF + 32 * 256)
#define SMEM_BYTES (SMEM_FLOATS * 4)       // 102400

__device__ __forceinline__ uint32_t pack_f16x2(float lo, float hi) {
    uint32_t d; asm("cvt.rn.f16x2.f32 %0, %1, %2;" : "=r"(d) : "f"(hi), "f"(lo)); return d;
}
__device__ __forceinline__ uint32_t hmax2z(uint32_t a) {
    uint32_t d; asm("max.f16x2 %0, %1, %2;" : "=r"(d) : "r"(a), "r"(0u)); return d;
}

// m16n8k8, f16 in / f16 out (D,C are 2x f16x2)
#define MMA8_H(D0,D1, A0,A1, B0, C0,C1) \
  asm("mma.sync.aligned.m16n8k8.row.col.f16.f16.f16.f16 " \
      "{%0,%1}, {%2,%3}, {%4}, {%5,%6};" \
      : "=r"(D0),"=r"(D1) : "r"(A0),"r"(A1), "r"(B0), "r"(C0),"r"(C1))

// m16n8k16, f16 in / fp32 acc
#define MMA16_F32(D0,D1,D2,D3, A0,A1,A2,A3, B0,B1, C0,C1,C2,C3) \
  asm("mma.sync.aligned.m16n8k16.row.col.f32.f16.f16.f32 " \
      "{%0,%1,%2,%3}, {%4,%5,%6,%7}, {%8,%9}, {%10,%11,%12,%13};" \
      : "=f"(D0),"=f"(D1),"=f"(D2),"=f"(D3) \
      : "r"(A0),"r"(A1),"r"(A2),"r"(A3), "r"(B0),"r"(B1), \
        "f"(C0),"f"(C1),"f"(C2),"f"(C3))

__global__ void __launch_bounds__(TPB, 1) qtb_kernel(
    const float* __restrict__ x, const float* __restrict__ theta, const float* __restrict__ phi,
    const float* __restrict__ W1, const float* __restrict__ b1,
    const float* __restrict__ W2, const float* __restrict__ b2,
    const float* __restrict__ g1, const float* __restrict__ be1,
    const float* __restrict__ g2, const float* __restrict__ be2,
    float* __restrict__ out)
{
    extern __shared__ float smem[];
    const int tid = threadIdx.x;
    uint4* pWB  = (uint4*)(smem + WB_OFF);
    uint2* pB16 = (uint2*)(smem + B16_OFF);

    // ================= preamble: fused weight + f16 bias tables =================
    for (int i = tid; i < 4096; i += TPB) {
        int cp = i >> 5, lane_ = i & 31;
        int gq = lane_ >> 2, tq = lane_ & 3;
        int c0 = cp * 2, c1 = c0 + 1;
        int f0 = c0 * 8 + gq, f1 = c1 * 8 + gq;
        uint4 v;
        v.x = pack_f16x2(W1[f0 * 8 + 2 * tq], W1[f0 * 8 + 2 * tq + 1]);
        v.y = pack_f16x2(W1[f1 * 8 + 2 * tq], W1[f1 * 8 + 2 * tq + 1]);
        v.z = pack_f16x2(W2[gq * 2048 + c0 * 8 + 2 * tq], W2[gq * 2048 + c0 * 8 + 2 * tq + 1]);
        v.w = pack_f16x2(W2[gq * 2048 + c1 * 8 + 2 * tq], W2[gq * 2048 + c1 * 8 + 2 * tq + 1]);
        pWB[i] = v;
    }
    for (int i = tid; i < 512; i += TPB) {
        int cp = i >> 2, tq = i & 3;
        int c0 = cp * 2, c1 = c0 + 1;
        uint2 v;
        v.x = pack_f16x2(b1[c0 * 8 + 2 * tq], b1[c0 * 8 + 2 * tq + 1]);
        v.y = pack_f16x2(b1[c1 * 8 + 2 * tq], b1[c1 * 8 + 2 * tq + 1]);
        pB16[i] = v;
    }
    __syncthreads();

    const int wid  = tid >> 5, lane = tid & 31;
    const int g    = lane >> 2, t = lane & 3;
    const int pair = wid >> 1, half = wid & 1;

    const int task = blockIdx.x * PAIRS_PER_BLOCK + pair;
    const bool act = (pair < PAIRS_PER_BLOCK) && (task < NTASKS);
    const int taskc = act ? task : 0;
    const int tok  = taskc * 32 + lane;            // one token per lane (2 tiles = 32 tokens)

    // ================= front: closed-form attn + LN1 + ffn_quantum (1 token/lane) ==========
    float h[8];
    {
        float th_[8], cph[8], gg_[8], bb_[8];
        #pragma unroll
        for (int j = 0; j < 8; j++) {
            th_[j] = __ldg(theta + j);
            cph[j] = cosf(__ldg(phi + j));
            gg_[j] = __ldg(g1 + j);
            bb_[j] = __ldg(be1 + j);
        }
        const float* xp = x + (size_t)tok * 8;
        float4 a4 = __ldg((const float4*)xp);
        float4 b4 = __ldg((const float4*)(xp + 4));
        float xv[8] = {a4.x, a4.y, a4.z, a4.w, b4.x, b4.y, b4.z, b4.w};

        float c_[8];
        #pragma unroll
        for (int j = 0; j < 8; j++) c_[j] = cosf(xv[j] + th_[j]);
        float attn[8];
        float pr = c_[0];
        #pragma unroll
        for (int j = 1; j < 8; j++) { pr *= c_[j]; attn[j] = pr; }
        float qr = c_[1];
        #pragma unroll
        for (int j = 2; j < 8; j++) qr *= c_[j];
        attn[0] = qr;

        float y[8]; float s = 0.f;
        #pragma unroll
        for (int j = 0; j < 8; j++) { y[j] = xv[j] + attn[j]; s += y[j]; }
        float m = s * 0.125f, v = 0.f;
        #pragma unroll
        for (int j = 0; j < 8; j++) { float d = y[j] - m; v += d * d; }
        float inv = rsqrtf(v * 0.125f + 1e-5f);

        float* sz = smem + SZ_OFF + wid * 256 + lane * 8;
        #pragma unroll
        for (int j = 0; j < 8; j++) {
            h[j] = (y[j] - m) * inv * gg_[j] + bb_[j];
            sz[j] = cph[j] * cosf(h[j]);           // z for this warp's private copy
        }
    }
    __syncwarp();

    // ================= A-frags: tile0 = rows 0-15, tile1 = rows 16-31 =================
    const float* z0 = smem + SZ_OFF + wid * 256;
    uint32_t A0g, A0G, A1g, A1G;
    {
        int i0 = g * 8 + 2 * t;
        A0g = pack_f16x2(z0[i0],       z0[i0 + 1]);        // tile0 row g
        A0G = pack_f16x2(z0[i0 + 64],  z0[i0 + 65]);       // tile0 row g+8
        A1g = pack_f16x2(z0[i0 + 128], z0[i0 + 129]);      // tile1 row g
        A1G = pack_f16x2(z0[i0 + 192], z0[i0 + 193]);      // tile1 row g+8
    }

    // ================= loop: this warp's 64 chunk-pairs (half of f) =================
    float acc0[4] = {0,0,0,0};
    float acc1[4] = {0,0,0,0};
    const int cpbase = half << 6;

    #pragma unroll 4
    for (int i = 0; i < 64; i++) {
        const int cp = cpbase + i;
        uint4 wq = pWB[(cp << 5) + lane];          // (w1c0, w1c1, w2c0, w2c1)
        uint2 bw = pB16[(cp << 2) + t];            // (bias c0, bias c1) f16x2

        uint32_t d00, d01, d10, d11;
        // ---- tile 0 ----
        MMA8_H(d00, d01, A0g, A0G, wq.x, bw.x, bw.x);       // chunk c0, f16 D + f16 bias C
        MMA8_H(d10, d11, A0g, A0G, wq.y, bw.y, bw.y);       // chunk c1
        d00 = hmax2z(d00); d01 = hmax2z(d01); d10 = hmax2z(d10); d11 = hmax2z(d11);
        MMA16_F32(acc0[0],acc0[1],acc0[2],acc0[3],
                  d00,d01,d10,d11, wq.z,wq.w,
                  acc0[0],acc0[1],acc0[2],acc0[3]);
        // ---- tile 1 ----
        MMA8_H(d00, d01, A1g, A1G, wq.x, bw.x, bw.x);
        MMA8_H(d10, d11, A1g, A1G, wq.y, bw.y, bw.y);
        d00 = hmax2z(d00); d01 = hmax2z(d01); d10 = hmax2z(d10); d11 = hmax2z(d11);
        MMA16_F32(acc1[0],acc1[1],acc1[2],acc1[3],
                  d00,d01,d10,d11, wq.z,wq.w,
                  acc1[0],acc1[1],acc1[2],acc1[3]);
    }

    // ================= exchange partial sums between the two f-halves =================
    __syncthreads();                                // z no longer needed anywhere
    float* sE = smem + SZ_OFF + wid * 256;          // own region: [32 tok][8 e]
    sE[(g)*8      + 2*t]     = acc0[0];
    sE[(g)*8      + 2*t + 1] = acc0[1];
    sE[(g+8)*8    + 2*t]     = acc0[2];
    sE[(g+8)*8    + 2*t + 1] = acc0[3];
    sE[(16+g)*8   + 2*t]     = acc1[0];
    sE[(16+g)*8   + 2*t + 1] = acc1[1];
    sE[(24+g)*8   + 2*t]     = acc1[2];
    sE[(24+g)*8   + 2*t + 1] = acc1[3];
    __syncthreads();

    // ================= epilogue (half-0 warps): residual + b2 + LN2, 1 token/lane ==========
    if (act && half == 0) {
        const float* sOwn = smem + SZ_OFF + wid * 256       + lane * 8;
        const float* sPar = smem + SZ_OFF + (wid ^ 1) * 256 + lane * 8;
        float w[8]; float s2 = 0.f;
        #pragma unroll
        for (int e = 0; e < 8; e++) {
            w[e] = h[e] + sOwn[e] + sPar[e] + __ldg(b2 + e);
            s2 += w[e];
        }
        float m2 = s2 * 0.125f, v2 = 0.f;
        #pragma unroll
        for (int e = 0; e < 8; e++) { float d = w[e] - m2; v2 += d * d; }
        float inv2 = rsqrtf(v2 * 0.125f + 1e-5f);
        float o[8];
        #pragma unroll
        for (int e = 0; e < 8; e++)
            o[e] = (w[e] - m2) * inv2 * __ldg(g2 + e) + __ldg(be2 + e);
        float* op = out + (size_t)tok * 8;
        *(float4*)op       = make_float4(o[0], o[1], o[2], o[3]);
        *(float4*)(op + 4) = make_float4(o[4], o[5], o[6], o[7]);
    }
}

extern "C" void kernel_launch(void* const* d_in, const int* in_sizes, int n_in,
                              void* d_out, int out_size) {
    const float* x      = (const float*)d_in[0];
    const float* theta  = (const float*)d_in[1];
    const float* phi    = (const float*)d_in[2];
    const float* W1     = (const float*)d_in[3];
    const float* b1     = (const float*)d_in[4];
    const float* W2     = (const float*)d_in[5];
    const float* b2     = (const float*)d_in[6];
    const float* gamma1 = (const float*)d_in[7];
    const float* beta1  = (const float*)d_in[8];
    const float* gamma2 = (const float*)d_in[9];
    const float* beta2  = (const float*)d_in[10];
    float* out = (float*)d_out;

    cudaFuncSetAttribute(qtb_kernel, cudaFuncAttributeMaxDynamicSharedMemorySize, SMEM_BYTES);
    qtb_kernel<<<GRID, TPB, SMEM_BYTES>>>(x, theta, phi, W1, b1, W2, b2,
                                          gamma1, beta1, gamma2, beta2, out);
}

// round 13
// speedup vs baseline: 4.6296x; 1.1699x over previous
#include <cuda_runtime.h>
#include <cuda_fp16.h>
#include <math.h>
#include <stdint.h>

// QuantumTransformerBlock — closed-form quantum ops + fp16 tensor-core FFN, f-split warp pairs.
// R13: (1) weight/bias table packing hoisted into a tiny pack-kernel writing __device__
// scratch (main kernel preamble = coalesced copy); (2) fast __cosf in the front section.
// Loop (R12): warp pair shares 2 tiles, each warp half the f-range; GEMM1 mma.m16n8k8.f16
// with f16 D/C (bias in C, relu = max.f16x2, D-regs feed GEMM2 A directly);
// GEMM2 chunk-paired mma.m16n8k16 fp32 acc.

#define TPB   1024
#define GRID  148
#define NTASKS 2048
#define PAIRS_PER_BLOCK 14     // 148*14 = 2072 >= 2048

// smem layout (floats)
#define WB_OFF   0        // 16384 u32 as uint4[4096]: [128 cp][32 lane] (w1c0,w1c1,w2c0,w2c1)
#define B16_OFF  16384    // 1024 u32 as uint2[512]: [128 cp][4 t] (bias f16x2 c0, c1)
#define SZ_OFF   17408    // 8192 floats: [32 warp][32 tok][8 j]  z, later partial-sum exchange
#define SMEM_FLOATS (SZ_OFF + 32 * 256)
#define SMEM_BYTES (SMEM_FLOATS * 4)       // 102400

__device__ uint4 g_wb[4096];
__device__ uint2 g_b16[512];

__device__ __forceinline__ uint32_t pack_f16x2(float lo, float hi) {
    uint32_t d; asm("cvt.rn.f16x2.f32 %0, %1, %2;" : "=r"(d) : "f"(hi), "f"(lo)); return d;
}
__device__ __forceinline__ uint32_t hmax2z(uint32_t a) {
    uint32_t d; asm("max.f16x2 %0, %1, %2;" : "=r"(d) : "r"(a), "r"(0u)); return d;
}

#define MMA8_H(D0,D1, A0,A1, B0, C0,C1) \
  asm("mma.sync.aligned.m16n8k8.row.col.f16.f16.f16.f16 " \
      "{%0,%1}, {%2,%3}, {%4}, {%5,%6};" \
      : "=r"(D0),"=r"(D1) : "r"(A0),"r"(A1), "r"(B0), "r"(C0),"r"(C1))

#define MMA16_F32(D0,D1,D2,D3, A0,A1,A2,A3, B0,B1, C0,C1,C2,C3) \
  asm("mma.sync.aligned.m16n8k16.row.col.f32.f16.f16.f32 " \
      "{%0,%1,%2,%3}, {%4,%5,%6,%7}, {%8,%9}, {%10,%11,%12,%13};" \
      : "=f"(D0),"=f"(D1),"=f"(D2),"=f"(D3) \
      : "r"(A0),"r"(A1),"r"(A2),"r"(A3), "r"(B0),"r"(B1), \
        "f"(C0),"f"(C1),"f"(C2),"f"(C3))

// ---------- pack kernel: build fused mma-fragment tables once ----------
__global__ void qtb_pack(const float* __restrict__ W1, const float* __restrict__ b1,
                         const float* __restrict__ W2)
{
    int i = blockIdx.x * 256 + threadIdx.x;        // [0, 4096)
    {
        int cp = i >> 5, lane_ = i & 31;
        int gq = lane_ >> 2, tq = lane_ & 3;
        int c0 = cp * 2, c1 = c0 + 1;
        int f0 = c0 * 8 + gq, f1 = c1 * 8 + gq;
        uint4 v;
        v.x = pack_f16x2(W1[f0 * 8 + 2 * tq], W1[f0 * 8 + 2 * tq + 1]);
        v.y = pack_f16x2(W1[f1 * 8 + 2 * tq], W1[f1 * 8 + 2 * tq + 1]);
        v.z = pack_f16x2(W2[gq * 2048 + c0 * 8 + 2 * tq], W2[gq * 2048 + c0 * 8 + 2 * tq + 1]);
        v.w = pack_f16x2(W2[gq * 2048 + c1 * 8 + 2 * tq], W2[gq * 2048 + c1 * 8 + 2 * tq + 1]);
        g_wb[i] = v;
    }
    if (i < 512) {
        int cp = i >> 2, tq = i & 3;
        int c0 = cp * 2, c1 = c0 + 1;
        uint2 v;
        v.x = pack_f16x2(b1[c0 * 8 + 2 * tq], b1[c0 * 8 + 2 * tq + 1]);
        v.y = pack_f16x2(b1[c1 * 8 + 2 * tq], b1[c1 * 8 + 2 * tq + 1]);
        g_b16[i] = v;
    }
}

// ---------- main kernel ----------
__global__ void __launch_bounds__(TPB, 1) qtb_kernel(
    const float* __restrict__ x, const float* __restrict__ theta, const float* __restrict__ phi,
    const float* __restrict__ b2,
    const float* __restrict__ g1, const float* __restrict__ be1,
    const float* __restrict__ g2, const float* __restrict__ be2,
    float* __restrict__ out)
{
    extern __shared__ float smem[];
    const int tid = threadIdx.x;
    uint4* pWB  = (uint4*)(smem + WB_OFF);
    uint2* pB16 = (uint2*)(smem + B16_OFF);

    // preamble: coalesced copy of prepacked tables (L2-hot)
    #pragma unroll
    for (int k = 0; k < 4; k++) pWB[tid + k * TPB] = g_wb[tid + k * TPB];
    if (tid < 512) pB16[tid] = g_b16[tid];

    const int wid  = tid >> 5, lane = tid & 31;
    const int g    = lane >> 2, t = lane & 3;
    const int pair = wid >> 1, half = wid & 1;

    const int task = blockIdx.x * PAIRS_PER_BLOCK + pair;
    const bool act = (pair < PAIRS_PER_BLOCK) && (task < NTASKS);
    const int taskc = act ? task : 0;
    const int tok  = taskc * 32 + lane;            // one token per lane

    // ---- front: closed-form attn + LN1 + ffn_quantum (fast __cosf) ----
    float h[8];
    {
        float th_[8], cph[8], gg_[8], bb_[8];
        #pragma unroll
        for (int j = 0; j < 8; j++) {
            th_[j] = __ldg(theta + j);
            cph[j] = __cosf(__ldg(phi + j));
            gg_[j] = __ldg(g1 + j);
            bb_[j] = __ldg(be1 + j);
        }
        const float* xp = x + (size_t)tok * 8;
        float4 a4 = __ldg((const float4*)xp);
        float4 b4 = __ldg((const float4*)(xp + 4));
        float xv[8] = {a4.x, a4.y, a4.z, a4.w, b4.x, b4.y, b4.z, b4.w};

        float c_[8];
        #pragma unroll
        for (int j = 0; j < 8; j++) c_[j] = __cosf(xv[j] + th_[j]);
        float attn[8];
        float pr = c_[0];
        #pragma unroll
        for (int j = 1; j < 8; j++) { pr *= c_[j]; attn[j] = pr; }
        float qr = c_[1];
        #pragma unroll
        for (int j = 2; j < 8; j++) qr *= c_[j];
        attn[0] = qr;

        float y[8]; float s = 0.f;
        #pragma unroll
        for (int j = 0; j < 8; j++) { y[j] = xv[j] + attn[j]; s += y[j]; }
        float m = s * 0.125f, v = 0.f;
        #pragma unroll
        for (int j = 0; j < 8; j++) { float d = y[j] - m; v += d * d; }
        float inv = rsqrtf(v * 0.125f + 1e-5f);

        float* sz = smem + SZ_OFF + wid * 256 + lane * 8;
        #pragma unroll
        for (int j = 0; j < 8; j++) {
            h[j] = (y[j] - m) * inv * gg_[j] + bb_[j];
            sz[j] = cph[j] * __cosf(h[j]);         // z
        }
    }
    __syncthreads();                                // tables + z ready

    // ---- A-frags: tile0 = rows 0-15, tile1 = rows 16-31 ----
    const float* z0 = smem + SZ_OFF + wid * 256;
    uint32_t A0g, A0G, A1g, A1G;
    {
        int i0 = g * 8 + 2 * t;
        A0g = pack_f16x2(z0[i0],       z0[i0 + 1]);
        A0G = pack_f16x2(z0[i0 + 64],  z0[i0 + 65]);
        A1g = pack_f16x2(z0[i0 + 128], z0[i0 + 129]);
        A1G = pack_f16x2(z0[i0 + 192], z0[i0 + 193]);
    }

    // ---- loop: this warp's 64 chunk-pairs (half of f) ----
    float acc0[4] = {0,0,0,0};
    float acc1[4] = {0,0,0,0};
    const int cpbase = half << 6;
    const uint4* wp = pWB + (cpbase << 5) + lane;
    const uint2* bp = pB16 + (cpbase << 2) + t;

    #pragma unroll 4
    for (int i = 0; i < 64; i++) {
        uint4 wq = wp[i << 5];
        uint2 bw = bp[i << 2];

        uint32_t d00, d01, d10, d11;
        MMA8_H(d00, d01, A0g, A0G, wq.x, bw.x, bw.x);
        MMA8_H(d10, d11, A0g, A0G, wq.y, bw.y, bw.y);
        d00 = hmax2z(d00); d01 = hmax2z(d01); d10 = hmax2z(d10); d11 = hmax2z(d11);
        MMA16_F32(acc0[0],acc0[1],acc0[2],acc0[3],
                  d00,d01,d10,d11, wq.z,wq.w,
                  acc0[0],acc0[1],acc0[2],acc0[3]);

        MMA8_H(d00, d01, A1g, A1G, wq.x, bw.x, bw.x);
        MMA8_H(d10, d11, A1g, A1G, wq.y, bw.y, bw.y);
        d00 = hmax2z(d00); d01 = hmax2z(d01); d10 = hmax2z(d10); d11 = hmax2z(d11);
        MMA16_F32(acc1[0],acc1[1],acc1[2],acc1[3],
                  d00,d01,d10,d11, wq.z,wq.w,
                  acc1[0],acc1[1],acc1[2],acc1[3]);
    }

    // ---- exchange partial sums between the two f-halves ----
    __syncthreads();
    float* sE = smem + SZ_OFF + wid * 256;
    sE[(g)*8      + 2*t]     = acc0[0];
    sE[(g)*8      + 2*t + 1] = acc0[1];
    sE[(g+8)*8    + 2*t]     = acc0[2];
    sE[(g+8)*8    + 2*t + 1] = acc0[3];
    sE[(16+g)*8   + 2*t]     = acc1[0];
    sE[(16+g)*8   + 2*t + 1] = acc1[1];
    sE[(24+g)*8   + 2*t]     = acc1[2];
    sE[(24+g)*8   + 2*t + 1] = acc1[3];
    __syncthreads();

    // ---- epilogue (half-0 warps): residual + b2 + LN2 ----
    if (act && half == 0) {
        const float* sOwn = smem + SZ_OFF + wid * 256       + lane * 8;
        const float* sPar = smem + SZ_OFF + (wid ^ 1) * 256 + lane * 8;
        float w[8]; float s2 = 0.f;
        #pragma unroll
        for (int e = 0; e < 8; e++) {
            w[e] = h[e] + sOwn[e] + sPar[e] + __ldg(b2 + e);
            s2 += w[e];
        }
        float m2 = s2 * 0.125f, v2 = 0.f;
        #pragma unroll
        for (int e = 0; e < 8; e++) { float d = w[e] - m2; v2 += d * d; }
        float inv2 = rsqrtf(v2 * 0.125f + 1e-5f);
        float o[8];
        #pragma unroll
        for (int e = 0; e < 8; e++)
            o[e] = (w[e] - m2) * inv2 * __ldg(g2 + e) + __ldg(be2 + e);
        float* op = out + (size_t)tok * 8;
        *(float4*)op       = make_float4(o[0], o[1], o[2], o[3]);
        *(float4*)(op + 4) = make_float4(o[4], o[5], o[6], o[7]);
    }
}

extern "C" void kernel_launch(void* const* d_in, const int* in_sizes, int n_in,
                              void* d_out, int out_size) {
    const float* x      = (const float*)d_in[0];
    const float* theta  = (const float*)d_in[1];
    const float* phi    = (const float*)d_in[2];
    const float* W1     = (const float*)d_in[3];
    const float* b1     = (const float*)d_in[4];
    const float* W2     = (const float*)d_in[5];
    const float* b2     = (const float*)d_in[6];
    const float* gamma1 = (const float*)d_in[7];
    const float* beta1  = (const float*)d_in[8];
    const float* gamma2 = (const float*)d_in[9];
    const float* beta2  = (const float*)d_in[10];
    float* out = (float*)d_out;

    qtb_pack<<<16, 256>>>(W1, b1, W2);
    cudaFuncSetAttribute(qtb_kernel, cudaFuncAttributeMaxDynamicSharedMemorySize, SMEM_BYTES);
    qtb_kernel<<<GRID, TPB, SMEM_BYTES>>>(x, theta, phi, b2,
                                          gamma1, beta1, gamma2, beta2, out);
}